// round 3
// baseline (speedup 1.0000x reference)
#include <cuda_runtime.h>
#include <math.h>
#include <stdint.h>

// Problem constants
constexpr int Bn   = 16;
constexpr int Nn   = 4096;
constexpr int Sn   = 1024;
constexpr int MPTS = Bn * Nn;   // 65536 query points
constexpr int MSRC = Bn * Sn;   // 16384 source points
constexpr int CO   = 128;

// ---------------- scratch (device globals; no allocation allowed) ----------
__device__ __align__(16) float g_p2w[MSRC * CO];   // points2 @ Wb^T
__device__ __align__(16) float g_t0[(size_t)MPTS * CO];
__device__ __align__(16) float g_t1[(size_t)MPTS * CO];
__device__ __align__(16) float g_t2[(size_t)MPTS * CO];
__device__ __align__(16) int   g_idx[MPTS * 3];
__device__ __align__(16) float g_w[MPTS * 3];
__device__ __align__(16) float g_stats[3 * 256];   // per layer: [sum(128), sumsq(128)]
__device__ __align__(16) float g_aff[3 * 256];     // per layer: [scale(128), shift(128)]

__device__ __forceinline__ float gelu_exact(float x) {
    return 0.5f * x * (1.0f + erff(x * 0.70710678118654752440f));
}

// ---------------- init: zero the stat accumulators --------------------------
__global__ void init_stats_kernel(float* stats) {
    stats[threadIdx.x] = 0.0f;   // launched with 768 threads
}

// ---------------- 3-NN + inverse-distance weights ---------------------------
// grid = Bn*32 blocks, 128 threads; each thread owns one query point.
__global__ void knn3_kernel(const float* __restrict__ xyz1,
                            const float* __restrict__ xyz2,
                            int* __restrict__ gidx,
                            float* __restrict__ gw) {
    __shared__ float4 sp[Sn];
    const int b = blockIdx.x >> 5;
    const int n = ((blockIdx.x & 31) << 7) + threadIdx.x;

    for (int s = threadIdx.x; s < Sn; s += 128) {
        const float* p = xyz2 + ((size_t)(b * Sn + s)) * 3;
        float x = p[0], y = p[1], z = p[2];
        sp[s] = make_float4(x, y, z, x * x + y * y + z * z);
    }
    __syncthreads();

    const int gi = b * Nn + n;
    const float* q = xyz1 + (size_t)gi * 3;
    const float x = q[0], y = q[1], z = q[2];
    const float n1 = x * x + y * y + z * z;

    float d0 = 3.4e38f, d1 = 3.4e38f, d2 = 3.4e38f;
    int   i0 = 0, i1 = 0, i2 = 0;

#pragma unroll 4
    for (int s = 0; s < Sn; s++) {
        float4 p = sp[s];
        float dot = fmaf(x, p.x, fmaf(y, p.y, z * p.z));
        float sq  = fmaf(-2.0f, dot, n1 + p.w);  // |x1|^2 + |x2|^2 - 2<x1,x2>
        if (sq < d2) {
            if (sq < d1) {
                d2 = d1; i2 = i1;
                if (sq < d0) { d1 = d0; i1 = i0; d0 = sq; i0 = s; }
                else         { d1 = sq; i1 = s; }
            } else { d2 = sq; i2 = s; }
        }
    }

    float e0 = sqrtf(fmaxf(d0, 1e-12f));
    float e1 = sqrtf(fmaxf(d1, 1e-12f));
    float e2 = sqrtf(fmaxf(d2, 1e-12f));
    float r0 = 1.0f / (e0 + 1e-8f);
    float r1 = 1.0f / (e1 + 1e-8f);
    float r2 = 1.0f / (e2 + 1e-8f);
    float inv = 1.0f / (r0 + r1 + r2);

    gidx[gi * 3 + 0] = i0; gidx[gi * 3 + 1] = i1; gidx[gi * 3 + 2] = i2;
    gw[gi * 3 + 0] = r0 * inv; gw[gi * 3 + 1] = r1 * inv; gw[gi * 3 + 2] = r2 * inv;
}

// ---------------- generic 128-wide GEMM --------------------------------------
// out[m, o] = op(A[m, :kdim]) @ W[o, :kdim]^T (+ bias) (+ gather) ; optional stats.
// Tile 128x128, 256 threads, 8x8 micro-tile per thread.
template <bool PRO, bool GATHER, bool STATS>
__global__ __launch_bounds__(256, 2)
void gemm128_kernel(const float* __restrict__ A, int kdim,
                    const float* __restrict__ W, int wstride,
                    const float* __restrict__ bias,
                    float* __restrict__ out,
                    const float* __restrict__ aff,    // [scale(128), shift(128)]
                    float* __restrict__ stats,        // [sum(128), sumsq(128)]
                    const int* __restrict__ gidx,
                    const float* __restrict__ gw,
                    const float* __restrict__ p2w) {
    __shared__ float As[16][132];
    __shared__ float Bs[16][128];
    __shared__ float csum[128];
    __shared__ float csum2[128];

    const int tid = threadIdx.x;
    const int tx  = tid & 15;
    const int ty  = tid >> 4;
    const int bm  = blockIdx.x << 7;

    if (STATS && tid < 128) { csum[tid] = 0.0f; csum2[tid] = 0.0f; }

    float acc[8][8];
#pragma unroll
    for (int i = 0; i < 8; i++)
#pragma unroll
        for (int j = 0; j < 8; j++) acc[i][j] = 0.0f;

    const int arow = tid >> 2;          // 0..63
    const int akc  = (tid & 3) << 2;    // 0,4,8,12

    for (int k0 = 0; k0 < kdim; k0 += 16) {
        // A tile (transposed into smem), optional BN-affine + GELU prologue
#pragma unroll
        for (int rr = 0; rr < 2; rr++) {
            int r = arow + (rr << 6);
            float4 v = *reinterpret_cast<const float4*>(
                A + (size_t)(bm + r) * kdim + k0 + akc);
            if (PRO) {
                int c = k0 + akc;
                v.x = gelu_exact(fmaf(aff[c + 0], v.x, aff[128 + c + 0]));
                v.y = gelu_exact(fmaf(aff[c + 1], v.y, aff[128 + c + 1]));
                v.z = gelu_exact(fmaf(aff[c + 2], v.z, aff[128 + c + 2]));
                v.w = gelu_exact(fmaf(aff[c + 3], v.w, aff[128 + c + 3]));
            }
            As[akc + 0][r] = v.x; As[akc + 1][r] = v.y;
            As[akc + 2][r] = v.z; As[akc + 3][r] = v.w;
        }
        // B tile: Bs[k][o] = W[o, k0+k]
#pragma unroll
        for (int p = 0; p < 8; p++) {
            int i = tid + (p << 8);
            int k = i >> 7, o = i & 127;
            Bs[k][o] = W[o * wstride + k0 + k];
        }
        __syncthreads();
#pragma unroll
        for (int k = 0; k < 16; k++) {
            float a[8], b[8];
            *reinterpret_cast<float4*>(&a[0]) =
                *reinterpret_cast<const float4*>(&As[k][ty << 3]);
            *reinterpret_cast<float4*>(&a[4]) =
                *reinterpret_cast<const float4*>(&As[k][(ty << 3) + 4]);
            *reinterpret_cast<float4*>(&b[0]) =
                *reinterpret_cast<const float4*>(&Bs[k][tx << 3]);
            *reinterpret_cast<float4*>(&b[4]) =
                *reinterpret_cast<const float4*>(&Bs[k][(tx << 3) + 4]);
#pragma unroll
            for (int i = 0; i < 8; i++)
#pragma unroll
                for (int j = 0; j < 8; j++)
                    acc[i][j] = fmaf(a[i], b[j], acc[i][j]);
        }
        __syncthreads();
    }

    // epilogue
    float bv[8];
#pragma unroll
    for (int j = 0; j < 8; j++) bv[j] = bias ? bias[(tx << 3) + j] : 0.0f;

    float cs[8], cs2[8];
#pragma unroll
    for (int j = 0; j < 8; j++) { cs[j] = 0.0f; cs2[j] = 0.0f; }

#pragma unroll
    for (int i = 0; i < 8; i++) {
        int m = bm + (ty << 3) + i;
        float vrow[8];
        if (GATHER) {
            int base = (m >> 12) << 17;  // batch * Sn * CO
            int j0 = gidx[3 * m + 0], j1 = gidx[3 * m + 1], j2 = gidx[3 * m + 2];
            float w0 = gw[3 * m + 0], w1 = gw[3 * m + 1], w2 = gw[3 * m + 2];
            const float4* p0 = reinterpret_cast<const float4*>(p2w + base + (j0 << 7) + (tx << 3));
            const float4* p1 = reinterpret_cast<const float4*>(p2w + base + (j1 << 7) + (tx << 3));
            const float4* p2 = reinterpret_cast<const float4*>(p2w + base + (j2 << 7) + (tx << 3));
            float4 a0 = p0[0], b0 = p0[1];
            float4 a1 = p1[0], b1 = p1[1];
            float4 a2 = p2[0], b2 = p2[1];
            vrow[0] = acc[i][0] + bv[0] + w0 * a0.x + w1 * a1.x + w2 * a2.x;
            vrow[1] = acc[i][1] + bv[1] + w0 * a0.y + w1 * a1.y + w2 * a2.y;
            vrow[2] = acc[i][2] + bv[2] + w0 * a0.z + w1 * a1.z + w2 * a2.z;
            vrow[3] = acc[i][3] + bv[3] + w0 * a0.w + w1 * a1.w + w2 * a2.w;
            vrow[4] = acc[i][4] + bv[4] + w0 * b0.x + w1 * b1.x + w2 * b2.x;
            vrow[5] = acc[i][5] + bv[5] + w0 * b0.y + w1 * b1.y + w2 * b2.y;
            vrow[6] = acc[i][6] + bv[6] + w0 * b0.z + w1 * b1.z + w2 * b2.z;
            vrow[7] = acc[i][7] + bv[7] + w0 * b0.w + w1 * b1.w + w2 * b2.w;
        } else {
#pragma unroll
            for (int j = 0; j < 8; j++) vrow[j] = acc[i][j] + bv[j];
        }
        float4* op = reinterpret_cast<float4*>(out + (size_t)m * 128 + (tx << 3));
        op[0] = make_float4(vrow[0], vrow[1], vrow[2], vrow[3]);
        op[1] = make_float4(vrow[4], vrow[5], vrow[6], vrow[7]);
        if (STATS) {
#pragma unroll
            for (int j = 0; j < 8; j++) {
                cs[j]  += vrow[j];
                cs2[j] += vrow[j] * vrow[j];
            }
        }
    }

    if (STATS) {
#pragma unroll
        for (int j = 0; j < 8; j++) {
            atomicAdd(&csum[(tx << 3) + j], cs[j]);
            atomicAdd(&csum2[(tx << 3) + j], cs2[j]);
        }
        __syncthreads();
        if (tid < 128) {
            atomicAdd(&stats[tid],        csum[tid]);
            atomicAdd(&stats[128 + tid],  csum2[tid]);
        }
    }
}

// ---------------- BN stat finalize: sums -> (scale, shift) -------------------
__global__ void finalize_stats_kernel(const float* __restrict__ stats,
                                      const float* __restrict__ g,
                                      const float* __restrict__ bt,
                                      float* __restrict__ aff) {
    int c = threadIdx.x;  // 128 threads
    const float invM = 1.0f / (float)MPTS;
    float mean = stats[c] * invM;
    float var  = stats[128 + c] * invM - mean * mean;
    float rstd = rsqrtf(var + 1e-5f);
    float sc = g[c] * rstd;
    aff[c]       = sc;
    aff[128 + c] = fmaf(-mean, sc, bt[c]);
}

// ---------------- final: out = gelu(bn2(t2) + gelu(bn0(t0))) -----------------
__global__ void final_kernel(const float* __restrict__ t0,
                             const float* __restrict__ t2,
                             const float* __restrict__ aff0,
                             const float* __restrict__ aff2,
                             float* __restrict__ out) {
    __shared__ float s0[128], h0[128], s2[128], h2[128];
    int tid = threadIdx.x;
    if (tid < 128) {
        s0[tid] = aff0[tid];       h0[tid] = aff0[128 + tid];
        s2[tid] = aff2[tid];       h2[tid] = aff2[128 + tid];
    }
    __syncthreads();

    size_t i4 = (size_t)blockIdx.x * blockDim.x + tid;  // float4 index
    float4 a = reinterpret_cast<const float4*>(t0)[i4];
    float4 b = reinterpret_cast<const float4*>(t2)[i4];
    int c = (int)(i4 & 31) << 2;

    float x0 = gelu_exact(fmaf(s0[c + 0], a.x, h0[c + 0]));
    float x1 = gelu_exact(fmaf(s0[c + 1], a.y, h0[c + 1]));
    float x2 = gelu_exact(fmaf(s0[c + 2], a.z, h0[c + 2]));
    float x3 = gelu_exact(fmaf(s0[c + 3], a.w, h0[c + 3]));

    float y0 = fmaf(s2[c + 0], b.x, h2[c + 0]) + x0;
    float y1 = fmaf(s2[c + 1], b.y, h2[c + 1]) + x1;
    float y2 = fmaf(s2[c + 2], b.z, h2[c + 2]) + x2;
    float y3 = fmaf(s2[c + 3], b.w, h2[c + 3]) + x3;

    reinterpret_cast<float4*>(out)[i4] =
        make_float4(gelu_exact(y0), gelu_exact(y1), gelu_exact(y2), gelu_exact(y3));
}

// ---------------- launch ------------------------------------------------------
extern "C" void kernel_launch(void* const* d_in, const int* in_sizes, int n_in,
                              void* d_out, int out_size) {
    const float* xyz1    = (const float*)d_in[0];
    const float* xyz2    = (const float*)d_in[1];
    const float* points1 = (const float*)d_in[2];
    const float* points2 = (const float*)d_in[3];
    const float* fuse_w  = (const float*)d_in[4];
    const float* fuse_b  = (const float*)d_in[5];
    const float* fuse_g  = (const float*)d_in[6];
    const float* fuse_bt = (const float*)d_in[7];
    const float* w1      = (const float*)d_in[8];
    const float* b1      = (const float*)d_in[9];
    const float* g1      = (const float*)d_in[10];
    const float* bt1     = (const float*)d_in[11];
    const float* w2      = (const float*)d_in[12];
    const float* b2      = (const float*)d_in[13];
    const float* g2      = (const float*)d_in[14];
    const float* bt2     = (const float*)d_in[15];
    float* out = (float*)d_out;

    float *p_p2w, *p_t0, *p_t1, *p_t2, *p_w, *p_stats, *p_aff;
    int* p_idx;
    cudaGetSymbolAddress((void**)&p_p2w,   g_p2w);
    cudaGetSymbolAddress((void**)&p_t0,    g_t0);
    cudaGetSymbolAddress((void**)&p_t1,    g_t1);
    cudaGetSymbolAddress((void**)&p_t2,    g_t2);
    cudaGetSymbolAddress((void**)&p_idx,   g_idx);
    cudaGetSymbolAddress((void**)&p_w,     g_w);
    cudaGetSymbolAddress((void**)&p_stats, g_stats);
    cudaGetSymbolAddress((void**)&p_aff,   g_aff);

    // zero stat accumulators (fresh every call; graph-replay safe)
    init_stats_kernel<<<1, 768>>>(p_stats);

    // 3-NN + weights
    knn3_kernel<<<Bn * 32, 128>>>(xyz1, xyz2, p_idx, p_w);

    // P2W = points2 @ fuse_w[:,128:384]^T   (no bias / stats / gather)
    gemm128_kernel<false, false, false><<<MSRC / 128, 256>>>(
        points2, 256, fuse_w + 128, 384, nullptr, p_p2w,
        nullptr, nullptr, nullptr, nullptr, nullptr);

    // t0 = points1 @ fuse_w[:,0:128]^T + fuse_b + gather(P2W) ; stats0
    gemm128_kernel<false, true, true><<<MPTS / 128, 256>>>(
        points1, 128, fuse_w, 384, fuse_b, p_t0,
        nullptr, p_stats + 0, p_idx, p_w, p_p2w);
    finalize_stats_kernel<<<1, 128>>>(p_stats + 0, fuse_g, fuse_bt, p_aff + 0);

    // t1 = gelu(bn0(t0)) @ w1^T + b1 ; stats1
    gemm128_kernel<true, false, true><<<MPTS / 128, 256>>>(
        p_t0, 128, w1, 128, b1, p_t1,
        p_aff + 0, p_stats + 256, nullptr, nullptr, nullptr);
    finalize_stats_kernel<<<1, 128>>>(p_stats + 256, g1, bt1, p_aff + 256);

    // t2 = gelu(bn1(t1)) @ w2^T + b2 ; stats2
    gemm128_kernel<true, false, true><<<MPTS / 128, 256>>>(
        p_t1, 128, w2, 128, b2, p_t2,
        p_aff + 256, p_stats + 512, nullptr, nullptr, nullptr);
    finalize_stats_kernel<<<1, 128>>>(p_stats + 512, g2, bt2, p_aff + 512);

    // out = gelu(bn2(t2) + gelu(bn0(t0)))
    final_kernel<<<(MPTS * 128 / 4) / 256, 256>>>(p_t0, p_t2, p_aff + 0, p_aff + 512, out);
}

// round 5
// speedup vs baseline: 1.5940x; 1.5940x over previous
#include <cuda_runtime.h>
#include <cuda_bf16.h>
#include <math.h>
#include <stdint.h>

// ---------------------------------------------------------------- constants
constexpr int Bn   = 16;
constexpr int Nn   = 4096;
constexpr int Sn   = 1024;
constexpr int MPTS = Bn * Nn;   // 65536
constexpr int MSRC = Bn * Sn;   // 16384
constexpr int CO   = 128;

// ---------------------------------------------------------------- scratch
__device__ __align__(16) float g_p2w[MSRC * CO];
__device__ __align__(16) float g_t0[(size_t)MPTS * CO];
__device__ __align__(16) float g_t1[(size_t)MPTS * CO];
__device__ __align__(16) float g_t2[(size_t)MPTS * CO];
__device__ __align__(16) int   g_idx[MPTS * 3];
__device__ __align__(16) float g_w[MPTS * 3];
__device__ __align__(16) float g_stats[3 * 256];
__device__ __align__(16) float g_aff[3 * 256];

__device__ __forceinline__ float gelu_exact(float x) {
    return 0.5f * x * (1.0f + erff(x * 0.70710678118654752440f));
}

// split fp32 pair into packed bf16 hi / lo(residual) words
__device__ __forceinline__ void split2(float a, float b, uint32_t& hi, uint32_t& lo) {
    __nv_bfloat16 ha = __float2bfloat16(a);
    __nv_bfloat16 hb = __float2bfloat16(b);
    __nv_bfloat16 la = __float2bfloat16(a - __bfloat162float(ha));
    __nv_bfloat16 lb = __float2bfloat16(b - __bfloat162float(hb));
    __nv_bfloat162 h; h.x = ha; h.y = hb;
    __nv_bfloat162 l; l.x = la; l.y = lb;
    hi = *reinterpret_cast<uint32_t*>(&h);
    lo = *reinterpret_cast<uint32_t*>(&l);
}

#define MMA16816(d, a, b0, b1)                                              \
    asm volatile(                                                           \
        "mma.sync.aligned.m16n8k16.row.col.f32.bf16.bf16.f32 "              \
        "{%0,%1,%2,%3}, {%4,%5,%6,%7}, {%8,%9}, {%0,%1,%2,%3};"             \
        : "+f"((d)[0]), "+f"((d)[1]), "+f"((d)[2]), "+f"((d)[3])            \
        : "r"((a)[0]), "r"((a)[1]), "r"((a)[2]), "r"((a)[3]),               \
          "r"(b0), "r"(b1))

// ---------------------------------------------------------------- small kernels
__global__ void init_stats_kernel(float* stats) { stats[threadIdx.x] = 0.0f; }

__global__ void knn3_kernel(const float* __restrict__ xyz1,
                            const float* __restrict__ xyz2,
                            int* __restrict__ gidx,
                            float* __restrict__ gw) {
    __shared__ float4 sp[Sn];
    const int b = blockIdx.x >> 5;
    const int n = ((blockIdx.x & 31) << 7) + threadIdx.x;

    for (int s = threadIdx.x; s < Sn; s += 128) {
        const float* p = xyz2 + ((size_t)(b * Sn + s)) * 3;
        float x = p[0], y = p[1], z = p[2];
        sp[s] = make_float4(x, y, z, x * x + y * y + z * z);
    }
    __syncthreads();

    const int gi = b * Nn + n;
    const float* q = xyz1 + (size_t)gi * 3;
    const float x = q[0], y = q[1], z = q[2];
    const float n1 = x * x + y * y + z * z;

    float d0 = 3.4e38f, d1 = 3.4e38f, d2 = 3.4e38f;
    int   i0 = 0, i1 = 0, i2 = 0;
#pragma unroll 4
    for (int s = 0; s < Sn; s++) {
        float4 p = sp[s];
        float dot = fmaf(x, p.x, fmaf(y, p.y, z * p.z));
        float sq  = fmaf(-2.0f, dot, n1 + p.w);
        if (sq < d2) {
            if (sq < d1) {
                d2 = d1; i2 = i1;
                if (sq < d0) { d1 = d0; i1 = i0; d0 = sq; i0 = s; }
                else         { d1 = sq; i1 = s; }
            } else { d2 = sq; i2 = s; }
        }
    }
    float e0 = sqrtf(fmaxf(d0, 1e-12f));
    float e1 = sqrtf(fmaxf(d1, 1e-12f));
    float e2 = sqrtf(fmaxf(d2, 1e-12f));
    float r0 = 1.0f / (e0 + 1e-8f);
    float r1 = 1.0f / (e1 + 1e-8f);
    float r2 = 1.0f / (e2 + 1e-8f);
    float inv = 1.0f / (r0 + r1 + r2);
    gidx[gi * 3 + 0] = i0; gidx[gi * 3 + 1] = i1; gidx[gi * 3 + 2] = i2;
    gw[gi * 3 + 0] = r0 * inv; gw[gi * 3 + 1] = r1 * inv; gw[gi * 3 + 2] = r2 * inv;
}

__global__ void finalize_stats_kernel(const float* __restrict__ stats,
                                      const float* __restrict__ g,
                                      const float* __restrict__ bt,
                                      float* __restrict__ aff) {
    int c = threadIdx.x;
    const float invM = 1.0f / (float)MPTS;
    float mean = stats[c] * invM;
    float var  = stats[128 + c] * invM - mean * mean;
    float rstd = rsqrtf(var + 1e-5f);
    float sc = g[c] * rstd;
    aff[c]       = sc;
    aff[128 + c] = fmaf(-mean, sc, bt[c]);
}

__global__ void final_kernel(const float* __restrict__ t0,
                             const float* __restrict__ t2,
                             const float* __restrict__ aff0,
                             const float* __restrict__ aff2,
                             float* __restrict__ out) {
    __shared__ float s0[128], h0[128], s2[128], h2[128];
    int tid = threadIdx.x;
    if (tid < 128) {
        s0[tid] = aff0[tid]; h0[tid] = aff0[128 + tid];
        s2[tid] = aff2[tid]; h2[tid] = aff2[128 + tid];
    }
    __syncthreads();
    size_t i4 = (size_t)blockIdx.x * blockDim.x + tid;
    float4 a = reinterpret_cast<const float4*>(t0)[i4];
    float4 b = reinterpret_cast<const float4*>(t2)[i4];
    int c = (int)(i4 & 31) << 2;
    float x0 = gelu_exact(fmaf(s0[c + 0], a.x, h0[c + 0]));
    float x1 = gelu_exact(fmaf(s0[c + 1], a.y, h0[c + 1]));
    float x2 = gelu_exact(fmaf(s0[c + 2], a.z, h0[c + 2]));
    float x3 = gelu_exact(fmaf(s0[c + 3], a.w, h0[c + 3]));
    float y0 = fmaf(s2[c + 0], b.x, h2[c + 0]) + x0;
    float y1 = fmaf(s2[c + 1], b.y, h2[c + 1]) + x1;
    float y2 = fmaf(s2[c + 2], b.z, h2[c + 2]) + x2;
    float y3 = fmaf(s2[c + 3], b.w, h2[c + 3]) + x3;
    reinterpret_cast<float4*>(out)[i4] =
        make_float4(gelu_exact(y0), gelu_exact(y1), gelu_exact(y2), gelu_exact(y3));
}

// ---------------------------------------------------------------- HMMA GEMM
// out[m, 0:128] = op(A[m, 0:KDIM]) @ W[0:128, 0:KDIM]^T (+bias)(+gather)(+stats)
// bf16 split-3 with fp32 register accumulators via mma.sync m16n8k16.
// 256 threads: 8 warps in 4(m) x 2(n); warp tile 32x64; CTA tile 128x128.
template <int KDIM, bool PRO, bool GATHER, bool STATS>
__global__ __launch_bounds__(256)
void mma_gemm(const float* __restrict__ A,
              const float* __restrict__ W, int wstride,
              const float* __restrict__ bias,
              float* __restrict__ out,
              const float* __restrict__ aff,
              float* __restrict__ stats,
              const int* __restrict__ gidx,
              const float* __restrict__ gw,
              const float* __restrict__ p2w,
              int ntiles) {
    extern __shared__ char sm[];
    constexpr int WPITCH  = KDIM * 2 + 16;            // bf16 row pitch (pad vs banks)
    constexpr int APITCH  = 80;                       // 32 bf16 + pad
    constexpr int OFF_WLO = 128 * WPITCH;
    constexpr int OFF_AHI = 2 * 128 * WPITCH;
    constexpr int OFF_ALO = OFF_AHI + 128 * APITCH;

    __shared__ float sBias[128];
    __shared__ float sAff[256];
    __shared__ float sSum[128], sSq[128];

    const int tid  = threadIdx.x;
    const int lane = tid & 31;
    const int w    = tid >> 5;
    const int wm   = w & 3;       // m group (32 rows)
    const int wn   = w >> 2;      // n group (64 cols)
    const int lg   = lane >> 2;   // 0..7
    const int lq   = lane & 3;    // 0..3

    if (tid < 128) {
        sBias[tid] = bias ? bias[tid] : 0.0f;
        if (STATS) { sSum[tid] = 0.0f; sSq[tid] = 0.0f; }
        if (PRO) { sAff[tid] = aff[tid]; sAff[128 + tid] = aff[128 + tid]; }
    }

    // ---- W -> smem bf16 hi/lo ([n][k], padded pitch) ----
    for (int idx = tid; idx < 128 * KDIM; idx += 256) {
        int n = idx / KDIM, k = idx % KDIM;
        float v = W[n * wstride + k];
        __nv_bfloat16 h = __float2bfloat16(v);
        __nv_bfloat16 l = __float2bfloat16(v - __bfloat162float(h));
        *reinterpret_cast<__nv_bfloat16*>(sm + n * WPITCH + k * 2) = h;
        *reinterpret_cast<__nv_bfloat16*>(sm + OFF_WLO + n * WPITCH + k * 2) = l;
    }
    __syncthreads();

    for (int t = blockIdx.x; t < ntiles; t += gridDim.x) {
        const float* Abase = A + (size_t)t * 128 * KDIM;

        float acc[2][8][4];
#pragma unroll
        for (int mi = 0; mi < 2; mi++)
#pragma unroll
            for (int nf = 0; nf < 8; nf++)
#pragma unroll
                for (int r = 0; r < 4; r++) acc[mi][nf][r] = 0.0f;

        for (int kc = 0; kc < KDIM / 32; kc++) {
            // ---- stage A chunk (128 rows x 32 k) fp32 -> bf16 hi/lo smem ----
#pragma unroll
            for (int q = 0; q < 4; q++) {
                int i = q * 256 + tid;           // 0..1023 float4s
                int row = i >> 3, kq = i & 7;
                float4 f = *reinterpret_cast<const float4*>(
                    Abase + (size_t)row * KDIM + kc * 32 + kq * 4);
                if (PRO) {
                    int c = kc * 32 + kq * 4;
                    f.x = gelu_exact(fmaf(sAff[c + 0], f.x, sAff[128 + c + 0]));
                    f.y = gelu_exact(fmaf(sAff[c + 1], f.y, sAff[128 + c + 1]));
                    f.z = gelu_exact(fmaf(sAff[c + 2], f.z, sAff[128 + c + 2]));
                    f.w = gelu_exact(fmaf(sAff[c + 3], f.w, sAff[128 + c + 3]));
                }
                uint32_t h0, l0, h1, l1;
                split2(f.x, f.y, h0, l0);
                split2(f.z, f.w, h1, l1);
                *reinterpret_cast<uint2*>(sm + OFF_AHI + row * APITCH + kq * 8) =
                    make_uint2(h0, h1);
                *reinterpret_cast<uint2*>(sm + OFF_ALO + row * APITCH + kq * 8) =
                    make_uint2(l0, l1);
            }
            __syncthreads();

#pragma unroll
            for (int ks = 0; ks < 2; ks++) {
                uint32_t ah[2][4], al[2][4];
#pragma unroll
                for (int mi = 0; mi < 2; mi++) {
                    int r = wm * 32 + mi * 16 + lg;
                    const char* p = sm + r * APITCH + ks * 32 + lq * 4;
                    ah[mi][0] = *(const uint32_t*)(p + OFF_AHI);
                    ah[mi][1] = *(const uint32_t*)(p + OFF_AHI + 8 * APITCH);
                    ah[mi][2] = *(const uint32_t*)(p + OFF_AHI + 16);
                    ah[mi][3] = *(const uint32_t*)(p + OFF_AHI + 8 * APITCH + 16);
                    al[mi][0] = *(const uint32_t*)(p + OFF_ALO);
                    al[mi][1] = *(const uint32_t*)(p + OFF_ALO + 8 * APITCH);
                    al[mi][2] = *(const uint32_t*)(p + OFF_ALO + 16);
                    al[mi][3] = *(const uint32_t*)(p + OFF_ALO + 8 * APITCH + 16);
                }
#pragma unroll
                for (int nf = 0; nf < 8; nf++) {
                    int n  = wn * 64 + nf * 8 + lg;
                    int kb = (kc * 32 + ks * 16) * 2 + lq * 4;
                    const char* pw = sm + n * WPITCH + kb;
                    uint32_t bh0 = *(const uint32_t*)pw;
                    uint32_t bh1 = *(const uint32_t*)(pw + 16);
                    uint32_t bl0 = *(const uint32_t*)(pw + OFF_WLO);
                    uint32_t bl1 = *(const uint32_t*)(pw + OFF_WLO + 16);
#pragma unroll
                    for (int mi = 0; mi < 2; mi++) {
                        MMA16816(acc[mi][nf], ah[mi], bh0, bh1);
                        MMA16816(acc[mi][nf], al[mi], bh0, bh1);
                        MMA16816(acc[mi][nf], ah[mi], bl0, bl1);
                    }
                }
            }
            __syncthreads();
        }

        // ---- epilogue: bias (+gather), store, stats ----
        float cS[16], cQ[16];
        if (STATS) {
#pragma unroll
            for (int i = 0; i < 16; i++) { cS[i] = 0.0f; cQ[i] = 0.0f; }
        }
#pragma unroll
        for (int mi = 0; mi < 2; mi++) {
#pragma unroll
            for (int rh = 0; rh < 2; rh++) {
                int r = wm * 32 + mi * 16 + rh * 8 + lg;
                int m = t * 128 + r;
                int j0 = 0, j1 = 0, j2 = 0, gb = 0;
                float w0 = 0.f, w1 = 0.f, w2 = 0.f;
                if (GATHER) {
                    j0 = gidx[3 * m + 0]; j1 = gidx[3 * m + 1]; j2 = gidx[3 * m + 2];
                    w0 = gw[3 * m + 0];   w1 = gw[3 * m + 1];   w2 = gw[3 * m + 2];
                    gb = (m >> 12) << 17;
                }
                float* orow = out + (size_t)m * 128;
#pragma unroll
                for (int nf = 0; nf < 8; nf++) {
                    int c0 = wn * 64 + nf * 8 + lq * 2;
                    float v0 = acc[mi][nf][rh * 2 + 0] + sBias[c0];
                    float v1 = acc[mi][nf][rh * 2 + 1] + sBias[c0 + 1];
                    if (GATHER) {
                        float2 a0 = *reinterpret_cast<const float2*>(p2w + gb + (j0 << 7) + c0);
                        float2 a1 = *reinterpret_cast<const float2*>(p2w + gb + (j1 << 7) + c0);
                        float2 a2 = *reinterpret_cast<const float2*>(p2w + gb + (j2 << 7) + c0);
                        v0 += w0 * a0.x + w1 * a1.x + w2 * a2.x;
                        v1 += w0 * a0.y + w1 * a1.y + w2 * a2.y;
                    }
                    *reinterpret_cast<float2*>(orow + c0) = make_float2(v0, v1);
                    if (STATS) {
                        cS[nf * 2 + 0] += v0;
                        cS[nf * 2 + 1] += v1;
                        cQ[nf * 2 + 0] = fmaf(v0, v0, cQ[nf * 2 + 0]);
                        cQ[nf * 2 + 1] = fmaf(v1, v1, cQ[nf * 2 + 1]);
                    }
                }
            }
        }
        if (STATS) {
#pragma unroll
            for (int i = 0; i < 16; i++) {
                cS[i] += __shfl_xor_sync(0xffffffffu, cS[i], 4);
                cQ[i] += __shfl_xor_sync(0xffffffffu, cQ[i], 4);
                cS[i] += __shfl_xor_sync(0xffffffffu, cS[i], 8);
                cQ[i] += __shfl_xor_sync(0xffffffffu, cQ[i], 8);
                cS[i] += __shfl_xor_sync(0xffffffffu, cS[i], 16);
                cQ[i] += __shfl_xor_sync(0xffffffffu, cQ[i], 16);
            }
            if (lane < 4) {
#pragma unroll
                for (int nf = 0; nf < 8; nf++) {
                    int c = wn * 64 + nf * 8 + lane * 2;
                    atomicAdd(&sSum[c],     cS[nf * 2 + 0]);
                    atomicAdd(&sSum[c + 1], cS[nf * 2 + 1]);
                    atomicAdd(&sSq[c],      cQ[nf * 2 + 0]);
                    atomicAdd(&sSq[c + 1],  cQ[nf * 2 + 1]);
                }
            }
        }
    }

    if (STATS) {
        __syncthreads();
        if (tid < 128) {
            atomicAdd(&stats[tid],       sSum[tid]);
            atomicAdd(&stats[128 + tid], sSq[tid]);
        }
    }
}

// ---------------------------------------------------------------- launch
extern "C" void kernel_launch(void* const* d_in, const int* in_sizes, int n_in,
                              void* d_out, int out_size) {
    const float* xyz1    = (const float*)d_in[0];
    const float* xyz2    = (const float*)d_in[1];
    const float* points1 = (const float*)d_in[2];
    const float* points2 = (const float*)d_in[3];
    const float* fuse_w  = (const float*)d_in[4];
    const float* fuse_b  = (const float*)d_in[5];
    const float* fuse_g  = (const float*)d_in[6];
    const float* fuse_bt = (const float*)d_in[7];
    const float* w1      = (const float*)d_in[8];
    const float* b1      = (const float*)d_in[9];
    const float* g1      = (const float*)d_in[10];
    const float* bt1     = (const float*)d_in[11];
    const float* w2      = (const float*)d_in[12];
    const float* b2      = (const float*)d_in[13];
    const float* g2      = (const float*)d_in[14];
    const float* bt2     = (const float*)d_in[15];
    float* out = (float*)d_out;

    float *p_p2w, *p_t0, *p_t1, *p_t2, *p_w, *p_stats, *p_aff;
    int* p_idx;
    cudaGetSymbolAddress((void**)&p_p2w,   g_p2w);
    cudaGetSymbolAddress((void**)&p_t0,    g_t0);
    cudaGetSymbolAddress((void**)&p_t1,    g_t1);
    cudaGetSymbolAddress((void**)&p_t2,    g_t2);
    cudaGetSymbolAddress((void**)&p_idx,   g_idx);
    cudaGetSymbolAddress((void**)&p_w,     g_w);
    cudaGetSymbolAddress((void**)&p_stats, g_stats);
    cudaGetSymbolAddress((void**)&p_aff,   g_aff);

    constexpr int SMEM_K128 = 2 * 128 * (128 * 2 + 16) + 2 * 128 * 80;  // 90112
    constexpr int SMEM_K256 = 2 * 128 * (256 * 2 + 16) + 2 * 128 * 80;  // 155648
    static bool attr_done = false;
    if (!attr_done) {
        cudaFuncSetAttribute(mma_gemm<256, false, false, false>,
                             cudaFuncAttributeMaxDynamicSharedMemorySize, SMEM_K256);
        cudaFuncSetAttribute(mma_gemm<128, false, true, true>,
                             cudaFuncAttributeMaxDynamicSharedMemorySize, SMEM_K128);
        cudaFuncSetAttribute(mma_gemm<128, true, false, true>,
                             cudaFuncAttributeMaxDynamicSharedMemorySize, SMEM_K128);
        attr_done = true;
    }

    init_stats_kernel<<<1, 768>>>(p_stats);
    knn3_kernel<<<Bn * 32, 128>>>(xyz1, xyz2, p_idx, p_w);

    // P2W = points2 @ fuse_w[:,128:384]^T   (16384 x 128, K=256)
    mma_gemm<256, false, false, false><<<MSRC / 128, 256, SMEM_K256>>>(
        points2, fuse_w + 128, 384, nullptr, p_p2w,
        nullptr, nullptr, nullptr, nullptr, nullptr, MSRC / 128);

    // t0 = points1 @ fuse_w[:,0:128]^T + fuse_b + gather(P2W) ; stats0
    mma_gemm<128, false, true, true><<<296, 256, SMEM_K128>>>(
        points1, fuse_w, 384, fuse_b, p_t0,
        nullptr, p_stats + 0, p_idx, p_w, p_p2w, MPTS / 128);
    finalize_stats_kernel<<<1, 128>>>(p_stats + 0, fuse_g, fuse_bt, p_aff + 0);

    // t1 = gelu(bn0(t0)) @ w1^T + b1 ; stats1
    mma_gemm<128, true, false, true><<<296, 256, SMEM_K128>>>(
        p_t0, w1, 128, b1, p_t1,
        p_aff + 0, p_stats + 256, nullptr, nullptr, nullptr, MPTS / 128);
    finalize_stats_kernel<<<1, 128>>>(p_stats + 256, g1, bt1, p_aff + 256);

    // t2 = gelu(bn1(t1)) @ w2^T + b2 ; stats2
    mma_gemm<128, true, false, true><<<296, 256, SMEM_K128>>>(
        p_t1, w2, 128, b2, p_t2,
        p_aff + 256, p_stats + 512, nullptr, nullptr, nullptr, MPTS / 128);
    finalize_stats_kernel<<<1, 128>>>(p_stats + 512, g2, bt2, p_aff + 512);

    // out = gelu(bn2(t2) + gelu(bn0(t0)))
    final_kernel<<<(MPTS * 128 / 4) / 256, 256>>>(p_t0, p_t2, p_aff + 0, p_aff + 512, out);
}

// round 8
// speedup vs baseline: 1.7788x; 1.1160x over previous
#include <cuda_runtime.h>
#include <cuda_bf16.h>
#include <math.h>
#include <stdint.h>

// ---------------------------------------------------------------- constants
constexpr int Bn   = 16;
constexpr int Nn   = 4096;
constexpr int Sn   = 1024;
constexpr int MPTS = Bn * Nn;   // 65536
constexpr int MSRC = Bn * Sn;   // 16384
constexpr int CO   = 128;

// ---------------------------------------------------------------- scratch
__device__ __align__(16) float g_p2w[MSRC * CO];
__device__ __align__(16) float g_t0[(size_t)MPTS * CO];
__device__ __align__(16) float g_t1[(size_t)MPTS * CO];
__device__ __align__(16) float g_t2[(size_t)MPTS * CO];
__device__ __align__(16) int   g_idx[MPTS * 3];
__device__ __align__(16) float g_w[MPTS * 3];
__device__ __align__(16) float g_stats[3 * 256];
__device__ __align__(16) float g_aff[3 * 256];

__device__ __forceinline__ float gelu_exact(float x) {
    return 0.5f * x * (1.0f + erff(x * 0.70710678118654752440f));
}

__device__ __forceinline__ void split2(float a, float b, uint32_t& hi, uint32_t& lo) {
    __nv_bfloat16 ha = __float2bfloat16(a);
    __nv_bfloat16 hb = __float2bfloat16(b);
    __nv_bfloat16 la = __float2bfloat16(a - __bfloat162float(ha));
    __nv_bfloat16 lb = __float2bfloat16(b - __bfloat162float(hb));
    __nv_bfloat162 h; h.x = ha; h.y = hb;
    __nv_bfloat162 l; l.x = la; l.y = lb;
    hi = *reinterpret_cast<uint32_t*>(&h);
    lo = *reinterpret_cast<uint32_t*>(&l);
}

#define MMA16816(d, a, b0, b1)                                              \
    asm volatile(                                                           \
        "mma.sync.aligned.m16n8k16.row.col.f32.bf16.bf16.f32 "              \
        "{%0,%1,%2,%3}, {%4,%5,%6,%7}, {%8,%9}, {%0,%1,%2,%3};"             \
        : "+f"((d)[0]), "+f"((d)[1]), "+f"((d)[2]), "+f"((d)[3])            \
        : "r"((a)[0]), "r"((a)[1]), "r"((a)[2]), "r"((a)[3]),               \
          "r"(b0), "r"(b1))

// ---------------------------------------------------------------- small kernels
__global__ void init_stats_kernel(float* stats) { stats[threadIdx.x] = 0.0f; }

__global__ void knn3_kernel(const float* __restrict__ xyz1,
                            const float* __restrict__ xyz2,
                            int* __restrict__ gidx,
                            float* __restrict__ gw) {
    __shared__ float4 sp[Sn];
    const int b = blockIdx.x >> 5;
    const int n = ((blockIdx.x & 31) << 7) + threadIdx.x;

    for (int s = threadIdx.x; s < Sn; s += 128) {
        const float* p = xyz2 + ((size_t)(b * Sn + s)) * 3;
        float x = p[0], y = p[1], z = p[2];
        sp[s] = make_float4(x, y, z, x * x + y * y + z * z);
    }
    __syncthreads();

    const int gi = b * Nn + n;
    const float* q = xyz1 + (size_t)gi * 3;
    const float x = q[0], y = q[1], z = q[2];
    const float n1 = x * x + y * y + z * z;

    float d0 = 3.4e38f, d1 = 3.4e38f, d2 = 3.4e38f;
    int   i0 = 0, i1 = 0, i2 = 0;
#pragma unroll 4
    for (int s = 0; s < Sn; s++) {
        float4 p = sp[s];
        float dot = fmaf(x, p.x, fmaf(y, p.y, z * p.z));
        float sq  = fmaf(-2.0f, dot, n1 + p.w);
        if (sq < d2) {
            if (sq < d1) {
                d2 = d1; i2 = i1;
                if (sq < d0) { d1 = d0; i1 = i0; d0 = sq; i0 = s; }
                else         { d1 = sq; i1 = s; }
            } else { d2 = sq; i2 = s; }
        }
    }
    float e0 = sqrtf(fmaxf(d0, 1e-12f));
    float e1 = sqrtf(fmaxf(d1, 1e-12f));
    float e2 = sqrtf(fmaxf(d2, 1e-12f));
    float r0 = 1.0f / (e0 + 1e-8f);
    float r1 = 1.0f / (e1 + 1e-8f);
    float r2 = 1.0f / (e2 + 1e-8f);
    float inv = 1.0f / (r0 + r1 + r2);
    gidx[gi * 3 + 0] = i0; gidx[gi * 3 + 1] = i1; gidx[gi * 3 + 2] = i2;
    gw[gi * 3 + 0] = r0 * inv; gw[gi * 3 + 1] = r1 * inv; gw[gi * 3 + 2] = r2 * inv;
}

__global__ void finalize_stats_kernel(const float* __restrict__ stats,
                                      const float* __restrict__ g,
                                      const float* __restrict__ bt,
                                      float* __restrict__ aff) {
    int c = threadIdx.x;
    const float invM = 1.0f / (float)MPTS;
    float mean = stats[c] * invM;
    float var  = stats[128 + c] * invM - mean * mean;
    float rstd = rsqrtf(var + 1e-5f);
    float sc = g[c] * rstd;
    aff[c]       = sc;
    aff[128 + c] = fmaf(-mean, sc, bt[c]);
}

__global__ void final_kernel(const float* __restrict__ t0,
                             const float* __restrict__ t2,
                             const float* __restrict__ aff0,
                             const float* __restrict__ aff2,
                             float* __restrict__ out) {
    __shared__ float s0[128], h0[128], s2[128], h2[128];
    int tid = threadIdx.x;
    if (tid < 128) {
        s0[tid] = aff0[tid]; h0[tid] = aff0[128 + tid];
        s2[tid] = aff2[tid]; h2[tid] = aff2[128 + tid];
    }
    __syncthreads();
    size_t i4 = (size_t)blockIdx.x * blockDim.x + tid;
    float4 a = reinterpret_cast<const float4*>(t0)[i4];
    float4 b = reinterpret_cast<const float4*>(t2)[i4];
    int c = (int)(i4 & 31) << 2;
    float x0 = gelu_exact(fmaf(s0[c + 0], a.x, h0[c + 0]));
    float x1 = gelu_exact(fmaf(s0[c + 1], a.y, h0[c + 1]));
    float x2 = gelu_exact(fmaf(s0[c + 2], a.z, h0[c + 2]));
    float x3 = gelu_exact(fmaf(s0[c + 3], a.w, h0[c + 3]));
    float y0 = fmaf(s2[c + 0], b.x, h2[c + 0]) + x0;
    float y1 = fmaf(s2[c + 1], b.y, h2[c + 1]) + x1;
    float y2 = fmaf(s2[c + 2], b.z, h2[c + 2]) + x2;
    float y3 = fmaf(s2[c + 3], b.w, h2[c + 3]) + x3;
    reinterpret_cast<float4*>(out)[i4] =
        make_float4(gelu_exact(y0), gelu_exact(y1), gelu_exact(y2), gelu_exact(y3));
}

// ---------------------------------------------------------------- HMMA GEMM
// out[m, 0:128] = op(A[m, 0:KDIM]) @ W[0:128, 0:KDIM]^T (+bias)(+gather)(+stats)
// bf16 split-3 via mma.sync m16n8k16; 2 CTAs/SM; register-prefetch pipeline.
template <int KDIM, bool PRO, bool GATHER, bool STATS>
__global__ __launch_bounds__(256, 2)
void mma_gemm(const float* __restrict__ A,
              const float* __restrict__ W, int wstride,
              const float* __restrict__ bias,
              float* __restrict__ out,
              const float* __restrict__ aff,
              float* __restrict__ stats,
              const int* __restrict__ gidx,
              const float* __restrict__ gw,
              const float* __restrict__ p2w,
              int ntiles) {
    extern __shared__ char sm[];
    constexpr int WPITCH  = KDIM * 2 + 16;
    constexpr int APITCH  = 80;
    constexpr int OFF_WLO = 128 * WPITCH;
    constexpr int OFF_AHI = 2 * 128 * WPITCH;
    constexpr int OFF_ALO = OFF_AHI + 128 * APITCH;
    constexpr int NCH     = KDIM / 32;

    __shared__ float sBias[128];
    __shared__ float sAff[256];
    __shared__ float sSum[128], sSq[128];

    const int tid  = threadIdx.x;
    const int lane = tid & 31;
    const int w    = tid >> 5;
    const int wm   = w & 3;
    const int wn   = w >> 2;
    const int lg   = lane >> 2;
    const int lq   = lane & 3;

    if (tid < 128) {
        sBias[tid] = bias ? bias[tid] : 0.0f;
        if (STATS) { sSum[tid] = 0.0f; sSq[tid] = 0.0f; }
        if (PRO) { sAff[tid] = aff[tid]; sAff[128 + tid] = aff[128 + tid]; }
    }

    // ---- W -> smem bf16 hi/lo ----
    for (int idx = tid; idx < 128 * KDIM; idx += 256) {
        int n = idx / KDIM, k = idx % KDIM;
        float v = W[n * wstride + k];
        __nv_bfloat16 h = __float2bfloat16(v);
        __nv_bfloat16 l = __float2bfloat16(v - __bfloat162float(h));
        *reinterpret_cast<__nv_bfloat16*>(sm + n * WPITCH + k * 2) = h;
        *reinterpret_cast<__nv_bfloat16*>(sm + OFF_WLO + n * WPITCH + k * 2) = l;
    }
    __syncthreads();

    const int prow = tid >> 3;          // staging row for this thread
    const int pkq  = tid & 7;           // staging k-quad

    for (int t = blockIdx.x; t < ntiles; t += gridDim.x) {
        const float* Abase = A + (size_t)t * 128 * KDIM;

        float acc[2][8][4];
#pragma unroll
        for (int mi = 0; mi < 2; mi++)
#pragma unroll
            for (int nf = 0; nf < 8; nf++)
#pragma unroll
                for (int r = 0; r < 4; r++) acc[mi][nf][r] = 0.0f;

        // prefetch chunk 0 into registers
        float4 pf[4];
#pragma unroll
        for (int q = 0; q < 4; q++)
            pf[q] = *reinterpret_cast<const float4*>(
                Abase + (size_t)(prow + q * 32) * KDIM + pkq * 4);

        for (int kc = 0; kc < NCH; kc++) {
            // ---- convert prefetched regs -> smem bf16 hi/lo ----
#pragma unroll
            for (int q = 0; q < 4; q++) {
                float4 f = pf[q];
                if (PRO) {
                    int c = kc * 32 + pkq * 4;
                    f.x = gelu_exact(fmaf(sAff[c + 0], f.x, sAff[128 + c + 0]));
                    f.y = gelu_exact(fmaf(sAff[c + 1], f.y, sAff[128 + c + 1]));
                    f.z = gelu_exact(fmaf(sAff[c + 2], f.z, sAff[128 + c + 2]));
                    f.w = gelu_exact(fmaf(sAff[c + 3], f.w, sAff[128 + c + 3]));
                }
                uint32_t h0, l0, h1, l1;
                split2(f.x, f.y, h0, l0);
                split2(f.z, f.w, h1, l1);
                int row = prow + q * 32;
                *reinterpret_cast<uint2*>(sm + OFF_AHI + row * APITCH + pkq * 8) =
                    make_uint2(h0, h1);
                *reinterpret_cast<uint2*>(sm + OFF_ALO + row * APITCH + pkq * 8) =
                    make_uint2(l0, l1);
            }
            __syncthreads();

            // ---- issue next chunk's loads (consumed after next sync) ----
            if (kc + 1 < NCH) {
#pragma unroll
                for (int q = 0; q < 4; q++)
                    pf[q] = *reinterpret_cast<const float4*>(
                        Abase + (size_t)(prow + q * 32) * KDIM + (kc + 1) * 32 + pkq * 4);
            }

            // ---- MMA on current chunk ----
#pragma unroll
            for (int ks = 0; ks < 2; ks++) {
                uint32_t ah[2][4], al[2][4];
#pragma unroll
                for (int mi = 0; mi < 2; mi++) {
                    int r = wm * 32 + mi * 16 + lg;
                    const char* p = sm + r * APITCH + ks * 32 + lq * 4;
                    ah[mi][0] = *(const uint32_t*)(p + OFF_AHI);
                    ah[mi][1] = *(const uint32_t*)(p + OFF_AHI + 8 * APITCH);
                    ah[mi][2] = *(const uint32_t*)(p + OFF_AHI + 16);
                    ah[mi][3] = *(const uint32_t*)(p + OFF_AHI + 8 * APITCH + 16);
                    al[mi][0] = *(const uint32_t*)(p + OFF_ALO);
                    al[mi][1] = *(const uint32_t*)(p + OFF_ALO + 8 * APITCH);
                    al[mi][2] = *(const uint32_t*)(p + OFF_ALO + 16);
                    al[mi][3] = *(const uint32_t*)(p + OFF_ALO + 8 * APITCH + 16);
                }
#pragma unroll
                for (int nf = 0; nf < 8; nf++) {
                    int n  = wn * 64 + nf * 8 + lg;
                    int kb = (kc * 32 + ks * 16) * 2 + lq * 4;
                    const char* pw = sm + n * WPITCH + kb;
                    uint32_t bh0 = *(const uint32_t*)pw;
                    uint32_t bh1 = *(const uint32_t*)(pw + 16);
                    uint32_t bl0 = *(const uint32_t*)(pw + OFF_WLO);
                    uint32_t bl1 = *(const uint32_t*)(pw + OFF_WLO + 16);
#pragma unroll
                    for (int mi = 0; mi < 2; mi++) {
                        MMA16816(acc[mi][nf], ah[mi], bh0, bh1);
                        MMA16816(acc[mi][nf], al[mi], bh0, bh1);
                        MMA16816(acc[mi][nf], ah[mi], bl0, bl1);
                    }
                }
            }
            __syncthreads();
        }

        // ---- epilogue: bias (+gather), store, stats ----
        float cS[16], cQ[16];
        if (STATS) {
#pragma unroll
            for (int i = 0; i < 16; i++) { cS[i] = 0.0f; cQ[i] = 0.0f; }
        }
#pragma unroll
        for (int mi = 0; mi < 2; mi++) {
#pragma unroll
            for (int rh = 0; rh < 2; rh++) {
                int r = wm * 32 + mi * 16 + rh * 8 + lg;
                int m = t * 128 + r;
                int j0 = 0, j1 = 0, j2 = 0, gb = 0;
                float w0 = 0.f, w1 = 0.f, w2 = 0.f;
                if (GATHER) {
                    j0 = gidx[3 * m + 0]; j1 = gidx[3 * m + 1]; j2 = gidx[3 * m + 2];
                    w0 = gw[3 * m + 0];   w1 = gw[3 * m + 1];   w2 = gw[3 * m + 2];
                    gb = (m >> 12) << 17;
                }
                float* orow = out + (size_t)m * 128;
#pragma unroll
                for (int nf = 0; nf < 8; nf++) {
                    int c0 = wn * 64 + nf * 8 + lq * 2;
                    float v0 = acc[mi][nf][rh * 2 + 0] + sBias[c0];
                    float v1 = acc[mi][nf][rh * 2 + 1] + sBias[c0 + 1];
                    if (GATHER) {
                        float2 a0 = *reinterpret_cast<const float2*>(p2w + gb + (j0 << 7) + c0);
                        float2 a1 = *reinterpret_cast<const float2*>(p2w + gb + (j1 << 7) + c0);
                        float2 a2 = *reinterpret_cast<const float2*>(p2w + gb + (j2 << 7) + c0);
                        v0 += w0 * a0.x + w1 * a1.x + w2 * a2.x;
                        v1 += w0 * a0.y + w1 * a1.y + w2 * a2.y;
                    }
                    *reinterpret_cast<float2*>(orow + c0) = make_float2(v0, v1);
                    if (STATS) {
                        cS[nf * 2 + 0] += v0;
                        cS[nf * 2 + 1] += v1;
                        cQ[nf * 2 + 0] = fmaf(v0, v0, cQ[nf * 2 + 0]);
                        cQ[nf * 2 + 1] = fmaf(v1, v1, cQ[nf * 2 + 1]);
                    }
                }
            }
        }
        if (STATS) {
#pragma unroll
            for (int i = 0; i < 16; i++) {
                cS[i] += __shfl_xor_sync(0xffffffffu, cS[i], 4);
                cQ[i] += __shfl_xor_sync(0xffffffffu, cQ[i], 4);
                cS[i] += __shfl_xor_sync(0xffffffffu, cS[i], 8);
                cQ[i] += __shfl_xor_sync(0xffffffffu, cQ[i], 8);
                cS[i] += __shfl_xor_sync(0xffffffffu, cS[i], 16);
                cQ[i] += __shfl_xor_sync(0xffffffffu, cQ[i], 16);
            }
            if (lane < 4) {
#pragma unroll
                for (int nf = 0; nf < 8; nf++) {
                    int c = wn * 64 + nf * 8 + lane * 2;
                    atomicAdd(&sSum[c],     cS[nf * 2 + 0]);
                    atomicAdd(&sSum[c + 1], cS[nf * 2 + 1]);
                    atomicAdd(&sSq[c],      cQ[nf * 2 + 0]);
                    atomicAdd(&sSq[c + 1],  cQ[nf * 2 + 1]);
                }
            }
        }
    }

    if (STATS) {
        __syncthreads();
        if (tid < 128) {
            atomicAdd(&stats[tid],       sSum[tid]);
            atomicAdd(&stats[128 + tid], sSq[tid]);
        }
    }
}

// ---------------------------------------------------------------- launch
extern "C" void kernel_launch(void* const* d_in, const int* in_sizes, int n_in,
                              void* d_out, int out_size) {
    const float* xyz1    = (const float*)d_in[0];
    const float* xyz2    = (const float*)d_in[1];
    const float* points1 = (const float*)d_in[2];
    const float* points2 = (const float*)d_in[3];
    const float* fuse_w  = (const float*)d_in[4];
    const float* fuse_b  = (const float*)d_in[5];
    const float* fuse_g  = (const float*)d_in[6];
    const float* fuse_bt = (const float*)d_in[7];
    const float* w1      = (const float*)d_in[8];
    const float* b1      = (const float*)d_in[9];
    const float* g1      = (const float*)d_in[10];
    const float* bt1     = (const float*)d_in[11];
    const float* w2      = (const float*)d_in[12];
    const float* b2      = (const float*)d_in[13];
    const float* g2      = (const float*)d_in[14];
    const float* bt2     = (const float*)d_in[15];
    float* out = (float*)d_out;

    float *p_p2w, *p_t0, *p_t1, *p_t2, *p_w, *p_stats, *p_aff;
    int* p_idx;
    cudaGetSymbolAddress((void**)&p_p2w,   g_p2w);
    cudaGetSymbolAddress((void**)&p_t0,    g_t0);
    cudaGetSymbolAddress((void**)&p_t1,    g_t1);
    cudaGetSymbolAddress((void**)&p_t2,    g_t2);
    cudaGetSymbolAddress((void**)&p_idx,   g_idx);
    cudaGetSymbolAddress((void**)&p_w,     g_w);
    cudaGetSymbolAddress((void**)&p_stats, g_stats);
    cudaGetSymbolAddress((void**)&p_aff,   g_aff);

    constexpr int SMEM_K128 = 2 * 128 * (128 * 2 + 16) + 2 * 128 * 80;  // 90112
    constexpr int SMEM_K256 = 2 * 128 * (256 * 2 + 16) + 2 * 128 * 80;  // 155648
    static bool attr_done = false;
    if (!attr_done) {
        cudaFuncSetAttribute(mma_gemm<256, false, false, false>,
                             cudaFuncAttributeMaxDynamicSharedMemorySize, SMEM_K256);
        cudaFuncSetAttribute(mma_gemm<128, false, true, true>,
                             cudaFuncAttributeMaxDynamicSharedMemorySize, SMEM_K128);
        cudaFuncSetAttribute(mma_gemm<128, true, false, true>,
                             cudaFuncAttributeMaxDynamicSharedMemorySize, SMEM_K128);
        attr_done = true;
    }

    init_stats_kernel<<<1, 768>>>(p_stats);
    knn3_kernel<<<Bn * 32, 128>>>(xyz1, xyz2, p_idx, p_w);

    // P2W = points2 @ fuse_w[:,128:384]^T   (16384 x 128, K=256)
    mma_gemm<256, false, false, false><<<MSRC / 128, 256, SMEM_K256>>>(
        points2, fuse_w + 128, 384, nullptr, p_p2w,
        nullptr, nullptr, nullptr, nullptr, nullptr, MSRC / 128);

    // t0 = points1 @ fuse_w[:,0:128]^T + fuse_b + gather(P2W) ; stats0
    mma_gemm<128, false, true, true><<<296, 256, SMEM_K128>>>(
        points1, fuse_w, 384, fuse_b, p_t0,
        nullptr, p_stats + 0, p_idx, p_w, p_p2w, MPTS / 128);
    finalize_stats_kernel<<<1, 128>>>(p_stats + 0, fuse_g, fuse_bt, p_aff + 0);

    // t1 = gelu(bn0(t0)) @ w1^T + b1 ; stats1
    mma_gemm<128, true, false, true><<<296, 256, SMEM_K128>>>(
        p_t0, w1, 128, b1, p_t1,
        p_aff + 0, p_stats + 256, nullptr, nullptr, nullptr, MPTS / 128);
    finalize_stats_kernel<<<1, 128>>>(p_stats + 256, g1, bt1, p_aff + 256);

    // t2 = gelu(bn1(t1)) @ w2^T + b2 ; stats2
    mma_gemm<128, true, false, true><<<296, 256, SMEM_K128>>>(
        p_t1, w2, 128, b2, p_t2,
        p_aff + 256, p_stats + 512, nullptr, nullptr, nullptr, MPTS / 128);
    finalize_stats_kernel<<<1, 128>>>(p_stats + 512, g2, bt2, p_aff + 512);

    // out = gelu(bn2(t2) + gelu(bn0(t0)))
    final_kernel<<<(MPTS * 128 / 4) / 256, 256>>>(p_t0, p_t2, p_aff + 0, p_aff + 512, out);
}

// round 10
// speedup vs baseline: 1.7808x; 1.0012x over previous
#include <cuda_runtime.h>
#include <cuda_bf16.h>
#include <math.h>
#include <stdint.h>

// ---------------------------------------------------------------- constants
constexpr int Bn   = 16;
constexpr int Nn   = 4096;
constexpr int Sn   = 1024;
constexpr int MPTS = Bn * Nn;   // 65536
constexpr int MSRC = Bn * Sn;   // 16384
constexpr int CO   = 128;

// ---------------------------------------------------------------- scratch
__device__ __align__(16) float g_p2w[MSRC * CO];
__device__ __align__(16) float g_t0[(size_t)MPTS * CO];
__device__ __align__(16) float g_t1[(size_t)MPTS * CO];
__device__ __align__(16) float g_t2[(size_t)MPTS * CO];
__device__ __align__(16) int   g_idx[MPTS * 3];
__device__ __align__(16) float g_w[MPTS * 3];
__device__ __align__(16) float g_stats[3 * 256];   // zero-initialized at load
__device__ __align__(16) float g_aff[3 * 256];

__device__ __forceinline__ float gelu_exact(float x) {
    return 0.5f * x * (1.0f + erff(x * 0.70710678118654752440f));
}

__device__ __forceinline__ void split2(float a, float b, uint32_t& hi, uint32_t& lo) {
    __nv_bfloat16 ha = __float2bfloat16(a);
    __nv_bfloat16 hb = __float2bfloat16(b);
    __nv_bfloat16 la = __float2bfloat16(a - __bfloat162float(ha));
    __nv_bfloat16 lb = __float2bfloat16(b - __bfloat162float(hb));
    __nv_bfloat162 h; h.x = ha; h.y = hb;
    __nv_bfloat162 l; l.x = la; l.y = lb;
    hi = *reinterpret_cast<uint32_t*>(&h);
    lo = *reinterpret_cast<uint32_t*>(&l);
}

__device__ __forceinline__ uint32_t smem_u32(const void* p) {
    uint32_t a;
    asm("{ .reg .u64 t; cvta.to.shared.u64 t, %1; cvt.u32.u64 %0, t; }"
        : "=r"(a) : "l"(p));
    return a;
}

#define MMA16816(d, a, b0, b1)                                              \
    asm volatile(                                                           \
        "mma.sync.aligned.m16n8k16.row.col.f32.bf16.bf16.f32 "              \
        "{%0,%1,%2,%3}, {%4,%5,%6,%7}, {%8,%9}, {%0,%1,%2,%3};"             \
        : "+f"((d)[0]), "+f"((d)[1]), "+f"((d)[2]), "+f"((d)[3])            \
        : "r"((a)[0]), "r"((a)[1]), "r"((a)[2]), "r"((a)[3]),               \
          "r"(b0), "r"(b1))

#define LDMX4(r, addr)                                                      \
    asm volatile(                                                           \
        "ldmatrix.sync.aligned.m8n8.x4.shared.b16 {%0,%1,%2,%3}, [%4];"     \
        : "=r"((r)[0]), "=r"((r)[1]), "=r"((r)[2]), "=r"((r)[3])            \
        : "r"(addr))

// ---------------------------------------------------------------- small kernels
__global__ void knn3_kernel(const float* __restrict__ xyz1,
                            const float* __restrict__ xyz2,
                            int* __restrict__ gidx,
                            float* __restrict__ gw) {
    __shared__ float4 sp[Sn];
    const int b = blockIdx.x >> 5;
    const int n = ((blockIdx.x & 31) << 7) + threadIdx.x;

    for (int s = threadIdx.x; s < Sn; s += 128) {
        const float* p = xyz2 + ((size_t)(b * Sn + s)) * 3;
        float x = p[0], y = p[1], z = p[2];
        sp[s] = make_float4(x, y, z, x * x + y * y + z * z);
    }
    __syncthreads();

    const int gi = b * Nn + n;
    const float* q = xyz1 + (size_t)gi * 3;
    const float x = q[0], y = q[1], z = q[2];
    const float n1 = x * x + y * y + z * z;

    float d0 = 3.4e38f, d1 = 3.4e38f, d2 = 3.4e38f;
    int   i0 = 0, i1 = 0, i2 = 0;
#pragma unroll 4
    for (int s = 0; s < Sn; s++) {
        float4 p = sp[s];
        float dot = fmaf(x, p.x, fmaf(y, p.y, z * p.z));
        float sq  = fmaf(-2.0f, dot, n1 + p.w);
        if (sq < d2) {
            if (sq < d1) {
                d2 = d1; i2 = i1;
                if (sq < d0) { d1 = d0; i1 = i0; d0 = sq; i0 = s; }
                else         { d1 = sq; i1 = s; }
            } else { d2 = sq; i2 = s; }
        }
    }
    float e0 = sqrtf(fmaxf(d0, 1e-12f));
    float e1 = sqrtf(fmaxf(d1, 1e-12f));
    float e2 = sqrtf(fmaxf(d2, 1e-12f));
    float r0 = 1.0f / (e0 + 1e-8f);
    float r1 = 1.0f / (e1 + 1e-8f);
    float r2 = 1.0f / (e2 + 1e-8f);
    float inv = 1.0f / (r0 + r1 + r2);
    gidx[gi * 3 + 0] = i0; gidx[gi * 3 + 1] = i1; gidx[gi * 3 + 2] = i2;
    gw[gi * 3 + 0] = r0 * inv; gw[gi * 3 + 1] = r1 * inv; gw[gi * 3 + 2] = r2 * inv;
}

// finalize BN affine, then zero the accumulators for the next call (graph-safe)
__global__ void finalize_stats_kernel(float* __restrict__ stats,
                                      const float* __restrict__ g,
                                      const float* __restrict__ bt,
                                      float* __restrict__ aff) {
    int c = threadIdx.x;
    const float invM = 1.0f / (float)MPTS;
    float mean = stats[c] * invM;
    float var  = stats[128 + c] * invM - mean * mean;
    float rstd = rsqrtf(var + 1e-5f);
    float sc = g[c] * rstd;
    aff[c]       = sc;
    aff[128 + c] = fmaf(-mean, sc, bt[c]);
    stats[c] = 0.0f;
    stats[128 + c] = 0.0f;
}

__global__ void final_kernel(const float* __restrict__ t0,
                             const float* __restrict__ t2,
                             const float* __restrict__ aff0,
                             const float* __restrict__ aff2,
                             float* __restrict__ out) {
    __shared__ float s0[128], h0[128], s2[128], h2[128];
    int tid = threadIdx.x;
    if (tid < 128) {
        s0[tid] = aff0[tid]; h0[tid] = aff0[128 + tid];
        s2[tid] = aff2[tid]; h2[tid] = aff2[128 + tid];
    }
    __syncthreads();
    size_t i4 = (size_t)blockIdx.x * blockDim.x + tid;
    float4 a = reinterpret_cast<const float4*>(t0)[i4];
    float4 b = reinterpret_cast<const float4*>(t2)[i4];
    int c = (int)(i4 & 31) << 2;
    float x0 = gelu_exact(fmaf(s0[c + 0], a.x, h0[c + 0]));
    float x1 = gelu_exact(fmaf(s0[c + 1], a.y, h0[c + 1]));
    float x2 = gelu_exact(fmaf(s0[c + 2], a.z, h0[c + 2]));
    float x3 = gelu_exact(fmaf(s0[c + 3], a.w, h0[c + 3]));
    float y0 = fmaf(s2[c + 0], b.x, h2[c + 0]) + x0;
    float y1 = fmaf(s2[c + 1], b.y, h2[c + 1]) + x1;
    float y2 = fmaf(s2[c + 2], b.z, h2[c + 2]) + x2;
    float y3 = fmaf(s2[c + 3], b.w, h2[c + 3]) + x3;
    reinterpret_cast<float4*>(out)[i4] =
        make_float4(gelu_exact(y0), gelu_exact(y1), gelu_exact(y2), gelu_exact(y3));
}

// ---------------------------------------------------------------- HMMA GEMM
// out[m,0:128] = op(A[m,0:KDIM]) @ W[0:128,0:KDIM]^T (+bias)(+gather)(+stats)
// bf16 split-3; 2 CTAs/SM; double-buffered A staging (1 sync/chunk);
// ldmatrix.x4 A-frags; k/k+8-interleaved W rows -> uint2 B-frags.
template <int KDIM, bool PRO, bool GATHER, bool STATS>
__global__ __launch_bounds__(256, 2)
void mma_gemm(const float* __restrict__ A,
              const float* __restrict__ W, int wstride,
              const float* __restrict__ bias,
              float* __restrict__ out,
              const float* __restrict__ aff,
              float* __restrict__ stats,
              const int* __restrict__ gidx,
              const float* __restrict__ gw,
              const float* __restrict__ p2w,
              int ntiles) {
    extern __shared__ char sm[];
    constexpr int WROW   = 4 * KDIM + 32;   // [hi 2K][lo 2K][pad 32]
    constexpr int WLO    = 2 * KDIM;
    constexpr int OFF_A  = 128 * WROW;
    constexpr int APITCH = 80;
    constexpr int ALO    = 128 * APITCH;    // 10240
    constexpr int ABUF   = 2 * ALO;         // 20480 (hi+lo per buffer)
    constexpr int AUX    = OFF_A + 2 * ABUF;
    constexpr int NCH    = KDIM / 32;

    float* sBias = reinterpret_cast<float*>(sm + AUX);
    float* sAff  = reinterpret_cast<float*>(sm + AUX + 512);
    float* sSum  = reinterpret_cast<float*>(sm + AUX + 1536);
    float* sSq   = reinterpret_cast<float*>(sm + AUX + 2048);

    const int tid  = threadIdx.x;
    const int lane = tid & 31;
    const int w    = tid >> 5;
    const int wm   = w & 3;
    const int wn   = w >> 2;
    const int lg   = lane >> 2;
    const int lq   = lane & 3;
    const uint32_t sbase = smem_u32(sm);

    if (tid < 128) {
        sBias[tid] = bias ? bias[tid] : 0.0f;
        if (STATS) { sSum[tid] = 0.0f; sSq[tid] = 0.0f; }
        if (PRO) { sAff[tid] = aff[tid]; sAff[128 + tid] = aff[128 + tid]; }
    }

    // ---- W -> smem bf16 hi/lo, k/k+8 interleaved within 16-k blocks ----
    for (int idx = tid; idx < 128 * KDIM; idx += 256) {
        int n = idx / KDIM, k = idx % KDIM;
        float v = W[n * wstride + k];
        __nv_bfloat16 h = __float2bfloat16(v);
        __nv_bfloat16 l = __float2bfloat16(v - __bfloat162float(h));
        int kk  = k & 15;
        int pos = ((kk & 7) >> 1) * 8 + ((kk >> 3) & 1) * 4 + (kk & 1) * 2;
        int off = n * WROW + (k >> 4) * 32 + pos;
        *reinterpret_cast<__nv_bfloat16*>(sm + off)       = h;
        *reinterpret_cast<__nv_bfloat16*>(sm + off + WLO) = l;
    }
    __syncthreads();

    const int prow = tid >> 3;          // staging row (0..31, +q*32)
    const int pkq  = tid & 7;           // staging k-quad

    for (int t = blockIdx.x; t < ntiles; t += gridDim.x) {
        const float* Abase = A + (size_t)t * 128 * KDIM;

        float acc[2][8][4];
#pragma unroll
        for (int mi = 0; mi < 2; mi++)
#pragma unroll
            for (int nf = 0; nf < 8; nf++)
#pragma unroll
                for (int r = 0; r < 4; r++) acc[mi][nf][r] = 0.0f;

        // prefetch chunk 0
        float4 pf[4];
#pragma unroll
        for (int q = 0; q < 4; q++)
            pf[q] = *reinterpret_cast<const float4*>(
                Abase + (size_t)(prow + q * 32) * KDIM + pkq * 4);

        for (int kc = 0; kc < NCH; kc++) {
            const int bufo = OFF_A + (kc & 1) * ABUF;
            // ---- convert prefetched regs -> smem bf16 hi/lo (buffer kc&1) ----
#pragma unroll
            for (int q = 0; q < 4; q++) {
                float4 f = pf[q];
                if (PRO) {
                    int c = kc * 32 + pkq * 4;
                    f.x = gelu_exact(fmaf(sAff[c + 0], f.x, sAff[128 + c + 0]));
                    f.y = gelu_exact(fmaf(sAff[c + 1], f.y, sAff[128 + c + 1]));
                    f.z = gelu_exact(fmaf(sAff[c + 2], f.z, sAff[128 + c + 2]));
                    f.w = gelu_exact(fmaf(sAff[c + 3], f.w, sAff[128 + c + 3]));
                }
                uint32_t h0, l0, h1, l1;
                split2(f.x, f.y, h0, l0);
                split2(f.z, f.w, h1, l1);
                char* b = sm + bufo + (prow + q * 32) * APITCH + pkq * 8;
                *reinterpret_cast<uint2*>(b)       = make_uint2(h0, h1);
                *reinterpret_cast<uint2*>(b + ALO) = make_uint2(l0, l1);
            }
            __syncthreads();

            // ---- issue next chunk's loads (hidden under MMA) ----
            if (kc + 1 < NCH) {
#pragma unroll
                for (int q = 0; q < 4; q++)
                    pf[q] = *reinterpret_cast<const float4*>(
                        Abase + (size_t)(prow + q * 32) * KDIM + (kc + 1) * 32 + pkq * 4);
            }

            // ---- MMA on current buffer ----
            const uint32_t abase = sbase + bufo;
            const uint32_t lrow  = lane & 15;
            const uint32_t lkb   = (lane >> 4) << 4;
#pragma unroll
            for (int ks = 0; ks < 2; ks++) {
                uint32_t ah[2][4], al[2][4];
#pragma unroll
                for (int mi = 0; mi < 2; mi++) {
                    uint32_t ad = abase +
                        (wm * 32 + mi * 16 + lrow) * APITCH + ks * 32 + lkb;
                    LDMX4(ah[mi], ad);
                    LDMX4(al[mi], ad + ALO);
                }
#pragma unroll
                for (int nf = 0; nf < 8; nf++) {
                    const char* pw = sm + (wn * 64 + nf * 8 + lg) * WROW +
                                     (kc * 2 + ks) * 32 + lq * 8;
                    uint2 bh = *reinterpret_cast<const uint2*>(pw);
                    uint2 bl = *reinterpret_cast<const uint2*>(pw + WLO);
#pragma unroll
                    for (int mi = 0; mi < 2; mi++) {
                        MMA16816(acc[mi][nf], ah[mi], bh.x, bh.y);
                        MMA16816(acc[mi][nf], al[mi], bh.x, bh.y);
                        MMA16816(acc[mi][nf], ah[mi], bl.x, bl.y);
                    }
                }
            }
            // no trailing sync: next convert writes the other buffer
        }

        // ---- epilogue: bias (+gather), store, stats ----
        float cS[16], cQ[16];
        if (STATS) {
#pragma unroll
            for (int i = 0; i < 16; i++) { cS[i] = 0.0f; cQ[i] = 0.0f; }
        }
#pragma unroll
        for (int mi = 0; mi < 2; mi++) {
#pragma unroll
            for (int rh = 0; rh < 2; rh++) {
                int r = wm * 32 + mi * 16 + rh * 8 + lg;
                int m = t * 128 + r;
                int j0 = 0, j1 = 0, j2 = 0, gb = 0;
                float w0 = 0.f, w1 = 0.f, w2 = 0.f;
                if (GATHER) {
                    j0 = gidx[3 * m + 0]; j1 = gidx[3 * m + 1]; j2 = gidx[3 * m + 2];
                    w0 = gw[3 * m + 0];   w1 = gw[3 * m + 1];   w2 = gw[3 * m + 2];
                    gb = (m >> 12) << 17;
                }
                float* orow = out + (size_t)m * 128;
#pragma unroll
                for (int nf = 0; nf < 8; nf++) {
                    int c0 = wn * 64 + nf * 8 + lq * 2;
                    float v0 = acc[mi][nf][rh * 2 + 0] + sBias[c0];
                    float v1 = acc[mi][nf][rh * 2 + 1] + sBias[c0 + 1];
                    if (GATHER) {
                        float2 a0 = *reinterpret_cast<const float2*>(p2w + gb + (j0 << 7) + c0);
                        float2 a1 = *reinterpret_cast<const float2*>(p2w + gb + (j1 << 7) + c0);
                        float2 a2 = *reinterpret_cast<const float2*>(p2w + gb + (j2 << 7) + c0);
                        v0 += w0 * a0.x + w1 * a1.x + w2 * a2.x;
                        v1 += w0 * a0.y + w1 * a1.y + w2 * a2.y;
                    }
                    *reinterpret_cast<float2*>(orow + c0) = make_float2(v0, v1);
                    if (STATS) {
                        cS[nf * 2 + 0] += v0;
                        cS[nf * 2 + 1] += v1;
                        cQ[nf * 2 + 0] = fmaf(v0, v0, cQ[nf * 2 + 0]);
                        cQ[nf * 2 + 1] = fmaf(v1, v1, cQ[nf * 2 + 1]);
                    }
                }
            }
        }
        if (STATS) {
#pragma unroll
            for (int i = 0; i < 16; i++) {
                cS[i] += __shfl_xor_sync(0xffffffffu, cS[i], 4);
                cQ[i] += __shfl_xor_sync(0xffffffffu, cQ[i], 4);
                cS[i] += __shfl_xor_sync(0xffffffffu, cS[i], 8);
                cQ[i] += __shfl_xor_sync(0xffffffffu, cQ[i], 8);
                cS[i] += __shfl_xor_sync(0xffffffffu, cS[i], 16);
                cQ[i] += __shfl_xor_sync(0xffffffffu, cQ[i], 16);
            }
            if (lane < 4) {
#pragma unroll
                for (int nf = 0; nf < 8; nf++) {
                    int c = wn * 64 + nf * 8 + lane * 2;
                    atomicAdd(&sSum[c],     cS[nf * 2 + 0]);
                    atomicAdd(&sSum[c + 1], cS[nf * 2 + 1]);
                    atomicAdd(&sSq[c],      cQ[nf * 2 + 0]);
                    atomicAdd(&sSq[c + 1],  cQ[nf * 2 + 1]);
                }
            }
        }
    }

    if (STATS) {
        __syncthreads();
        if (tid < 128) {
            atomicAdd(&stats[tid],       sSum[tid]);
            atomicAdd(&stats[128 + tid], sSq[tid]);
        }
    }
}

// ---------------------------------------------------------------- launch
extern "C" void kernel_launch(void* const* d_in, const int* in_sizes, int n_in,
                              void* d_out, int out_size) {
    const float* xyz1    = (const float*)d_in[0];
    const float* xyz2    = (const float*)d_in[1];
    const float* points1 = (const float*)d_in[2];
    const float* points2 = (const float*)d_in[3];
    const float* fuse_w  = (const float*)d_in[4];
    const float* fuse_b  = (const float*)d_in[5];
    const float* fuse_g  = (const float*)d_in[6];
    const float* fuse_bt = (const float*)d_in[7];
    const float* w1      = (const float*)d_in[8];
    const float* b1      = (const float*)d_in[9];
    const float* g1      = (const float*)d_in[10];
    const float* bt1     = (const float*)d_in[11];
    const float* w2      = (const float*)d_in[12];
    const float* b2      = (const float*)d_in[13];
    const float* g2      = (const float*)d_in[14];
    const float* bt2     = (const float*)d_in[15];
    float* out = (float*)d_out;

    float *p_p2w, *p_t0, *p_t1, *p_t2, *p_w, *p_stats, *p_aff;
    int* p_idx;
    cudaGetSymbolAddress((void**)&p_p2w,   g_p2w);
    cudaGetSymbolAddress((void**)&p_t0,    g_t0);
    cudaGetSymbolAddress((void**)&p_t1,    g_t1);
    cudaGetSymbolAddress((void**)&p_t2,    g_t2);
    cudaGetSymbolAddress((void**)&p_idx,   g_idx);
    cudaGetSymbolAddress((void**)&p_w,     g_w);
    cudaGetSymbolAddress((void**)&p_stats, g_stats);
    cudaGetSymbolAddress((void**)&p_aff,   g_aff);

    // dyn smem: W(128*WROW) + 2 A buffers + 2560 aux
    constexpr int SMEM_K128 = 128 * (4 * 128 + 32) + 2 * 20480 + 2560;  // 113152
    constexpr int SMEM_K256 = 128 * (4 * 256 + 32) + 2 * 20480 + 2560;  // 178688
    static bool attr_done = false;
    if (!attr_done) {
        cudaFuncSetAttribute(mma_gemm<256, false, false, false>,
                             cudaFuncAttributeMaxDynamicSharedMemorySize, SMEM_K256);
        cudaFuncSetAttribute(mma_gemm<128, false, true, true>,
                             cudaFuncAttributeMaxDynamicSharedMemorySize, SMEM_K128);
        cudaFuncSetAttribute(mma_gemm<128, true, false, true>,
                             cudaFuncAttributeMaxDynamicSharedMemorySize, SMEM_K128);
        attr_done = true;
    }

    knn3_kernel<<<Bn * 32, 128>>>(xyz1, xyz2, p_idx, p_w);

    // P2W = points2 @ fuse_w[:,128:384]^T   (16384 x 128, K=256)
    mma_gemm<256, false, false, false><<<MSRC / 128, 256, SMEM_K256>>>(
        points2, fuse_w + 128, 384, nullptr, p_p2w,
        nullptr, nullptr, nullptr, nullptr, nullptr, MSRC / 128);

    // t0 = points1 @ fuse_w[:,0:128]^T + fuse_b + gather(P2W) ; stats0
    mma_gemm<128, false, true, true><<<296, 256, SMEM_K128>>>(
        points1, fuse_w, 384, fuse_b, p_t0,
        nullptr, p_stats + 0, p_idx, p_w, p_p2w, MPTS / 128);
    finalize_stats_kernel<<<1, 128>>>(p_stats + 0, fuse_g, fuse_bt, p_aff + 0);

    // t1 = gelu(bn0(t0)) @ w1^T + b1 ; stats1
    mma_gemm<128, true, false, true><<<296, 256, SMEM_K128>>>(
        p_t0, w1, 128, b1, p_t1,
        p_aff + 0, p_stats + 256, nullptr, nullptr, nullptr, MPTS / 128);
    finalize_stats_kernel<<<1, 128>>>(p_stats + 256, g1, bt1, p_aff + 256);

    // t2 = gelu(bn1(t1)) @ w2^T + b2 ; stats2
    mma_gemm<128, true, false, true><<<296, 256, SMEM_K128>>>(
        p_t1, w2, 128, b2, p_t2,
        p_aff + 256, p_stats + 512, nullptr, nullptr, nullptr, MPTS / 128);
    finalize_stats_kernel<<<1, 128>>>(p_stats + 512, g2, bt2, p_aff + 512);

    // out = gelu(bn2(t2) + gelu(bn0(t0)))
    final_kernel<<<(MPTS * 128 / 4) / 256, 256>>>(p_t0, p_t2, p_aff + 0, p_aff + 512, out);
}

// round 11
// speedup vs baseline: 1.7963x; 1.0087x over previous
#include <cuda_runtime.h>
#include <cuda_bf16.h>
#include <math.h>
#include <stdint.h>

// ---------------------------------------------------------------- constants
constexpr int Bn   = 16;
constexpr int Nn   = 4096;
constexpr int Sn   = 1024;
constexpr int MPTS = Bn * Nn;   // 65536
constexpr int MSRC = Bn * Sn;   // 16384
constexpr int CO   = 128;

// ---------------------------------------------------------------- scratch
__device__ __align__(16) float g_p2w[MSRC * CO];
__device__ __align__(16) float g_t0[(size_t)MPTS * CO];
__device__ __align__(16) float g_t1[(size_t)MPTS * CO];
__device__ __align__(16) float g_t2[(size_t)MPTS * CO];
__device__ __align__(16) int   g_idx[MPTS * 3];
__device__ __align__(16) float g_w[MPTS * 3];
__device__ __align__(16) float g_stats[3 * 256];   // zero-init at load; re-zeroed by knn3
__device__ __align__(16) float g_aff[3 * 256];     // (unused now, kept for layout stability)

__device__ __forceinline__ float gelu_exact(float x) {
    return 0.5f * x * (1.0f + erff(x * 0.70710678118654752440f));
}

__device__ __forceinline__ void split2(float a, float b, uint32_t& hi, uint32_t& lo) {
    __nv_bfloat16 ha = __float2bfloat16(a);
    __nv_bfloat16 hb = __float2bfloat16(b);
    __nv_bfloat16 la = __float2bfloat16(a - __bfloat162float(ha));
    __nv_bfloat16 lb = __float2bfloat16(b - __bfloat162float(hb));
    __nv_bfloat162 h; h.x = ha; h.y = hb;
    __nv_bfloat162 l; l.x = la; l.y = lb;
    hi = *reinterpret_cast<uint32_t*>(&h);
    lo = *reinterpret_cast<uint32_t*>(&l);
}

__device__ __forceinline__ uint32_t smem_u32(const void* p) {
    uint32_t a;
    asm("{ .reg .u64 t; cvta.to.shared.u64 t, %1; cvt.u32.u64 %0, t; }"
        : "=r"(a) : "l"(p));
    return a;
}

#define MMA16816(d, a, b0, b1)                                              \
    asm volatile(                                                           \
        "mma.sync.aligned.m16n8k16.row.col.f32.bf16.bf16.f32 "              \
        "{%0,%1,%2,%3}, {%4,%5,%6,%7}, {%8,%9}, {%0,%1,%2,%3};"             \
        : "+f"((d)[0]), "+f"((d)[1]), "+f"((d)[2]), "+f"((d)[3])            \
        : "r"((a)[0]), "r"((a)[1]), "r"((a)[2]), "r"((a)[3]),               \
          "r"(b0), "r"(b1))

#define LDMX4(r, addr)                                                      \
    asm volatile(                                                           \
        "ldmatrix.sync.aligned.m8n8.x4.shared.b16 {%0,%1,%2,%3}, [%4];"     \
        : "=r"((r)[0]), "=r"((r)[1]), "=r"((r)[2]), "=r"((r)[3])            \
        : "r"(addr))

#define BAR_PAIR(id)                                                        \
    asm volatile("bar.sync %0, %1;" :: "r"(id), "r"(64) : "memory")

// ---------------------------------------------------------------- small kernels
__global__ void knn3_kernel(const float* __restrict__ xyz1,
                            const float* __restrict__ xyz2,
                            int* __restrict__ gidx,
                            float* __restrict__ gw,
                            float* __restrict__ stats) {
    __shared__ float4 sp[Sn];
    const int b = blockIdx.x >> 5;
    const int n = ((blockIdx.x & 31) << 7) + threadIdx.x;

    // zero BN stat accumulators for this call (graph-replay safe)
    if (blockIdx.x == 0) {
#pragma unroll
        for (int i = 0; i < 6; i++) stats[i * 128 + threadIdx.x] = 0.0f;
    }

    for (int s = threadIdx.x; s < Sn; s += 128) {
        const float* p = xyz2 + ((size_t)(b * Sn + s)) * 3;
        float x = p[0], y = p[1], z = p[2];
        sp[s] = make_float4(x, y, z, x * x + y * y + z * z);
    }
    __syncthreads();

    const int gi = b * Nn + n;
    const float* q = xyz1 + (size_t)gi * 3;
    const float x = q[0], y = q[1], z = q[2];
    const float n1 = x * x + y * y + z * z;

    float d0 = 3.4e38f, d1 = 3.4e38f, d2 = 3.4e38f;
    int   i0 = 0, i1 = 0, i2 = 0;
#pragma unroll 4
    for (int s = 0; s < Sn; s++) {
        float4 p = sp[s];
        float dot = fmaf(x, p.x, fmaf(y, p.y, z * p.z));
        float sq  = fmaf(-2.0f, dot, n1 + p.w);
        if (sq < d2) {
            if (sq < d1) {
                d2 = d1; i2 = i1;
                if (sq < d0) { d1 = d0; i1 = i0; d0 = sq; i0 = s; }
                else         { d1 = sq; i1 = s; }
            } else { d2 = sq; i2 = s; }
        }
    }
    float e0 = sqrtf(fmaxf(d0, 1e-12f));
    float e1 = sqrtf(fmaxf(d1, 1e-12f));
    float e2 = sqrtf(fmaxf(d2, 1e-12f));
    float r0 = 1.0f / (e0 + 1e-8f);
    float r1 = 1.0f / (e1 + 1e-8f);
    float r2 = 1.0f / (e2 + 1e-8f);
    float inv = 1.0f / (r0 + r1 + r2);
    gidx[gi * 3 + 0] = i0; gidx[gi * 3 + 1] = i1; gidx[gi * 3 + 2] = i2;
    gw[gi * 3 + 0] = r0 * inv; gw[gi * 3 + 1] = r1 * inv; gw[gi * 3 + 2] = r2 * inv;
}

__global__ void final_kernel(const float* __restrict__ t0,
                             const float* __restrict__ t2,
                             const float* __restrict__ st0,
                             const float* __restrict__ g0,
                             const float* __restrict__ bt0,
                             const float* __restrict__ st2,
                             const float* __restrict__ g2,
                             const float* __restrict__ bt2,
                             float* __restrict__ out) {
    __shared__ float s0[128], h0[128], s2[128], h2[128];
    int tid = threadIdx.x;
    if (tid < 128) {
        const float invM = 1.0f / (float)MPTS;
        float m0 = st0[tid] * invM;
        float v0 = st0[128 + tid] * invM - m0 * m0;
        float sc0 = g0[tid] * rsqrtf(v0 + 1e-5f);
        s0[tid] = sc0; h0[tid] = fmaf(-m0, sc0, bt0[tid]);
        float m2 = st2[tid] * invM;
        float v2 = st2[128 + tid] * invM - m2 * m2;
        float sc2 = g2[tid] * rsqrtf(v2 + 1e-5f);
        s2[tid] = sc2; h2[tid] = fmaf(-m2, sc2, bt2[tid]);
    }
    __syncthreads();
    size_t i4 = (size_t)blockIdx.x * blockDim.x + tid;
    float4 a = reinterpret_cast<const float4*>(t0)[i4];
    float4 b = reinterpret_cast<const float4*>(t2)[i4];
    int c = (int)(i4 & 31) << 2;
    float x0 = gelu_exact(fmaf(s0[c + 0], a.x, h0[c + 0]));
    float x1 = gelu_exact(fmaf(s0[c + 1], a.y, h0[c + 1]));
    float x2 = gelu_exact(fmaf(s0[c + 2], a.z, h0[c + 2]));
    float x3 = gelu_exact(fmaf(s0[c + 3], a.w, h0[c + 3]));
    float y0 = fmaf(s2[c + 0], b.x, h2[c + 0]) + x0;
    float y1 = fmaf(s2[c + 1], b.y, h2[c + 1]) + x1;
    float y2 = fmaf(s2[c + 2], b.z, h2[c + 2]) + x2;
    float y3 = fmaf(s2[c + 3], b.w, h2[c + 3]) + x3;
    reinterpret_cast<float4*>(out)[i4] =
        make_float4(gelu_exact(y0), gelu_exact(y1), gelu_exact(y2), gelu_exact(y3));
}

// ---------------------------------------------------------------- HMMA GEMM
// out[m,0:128] = op(A[m,0:KDIM]) @ W[0:128,0:KDIM]^T (+bias)(+gather)(+stats)
// bf16 split-3; 2 CTAs/SM; per-warp-pair staging + 64-thread named barriers.
// PRO layers compute the BN affine in-kernel from raw stats (no finalize launch).
template <int KDIM, bool PRO, bool GATHER, bool STATS>
__global__ __launch_bounds__(256, 2)
void mma_gemm(const float* __restrict__ A,
              const float* __restrict__ W, int wstride,
              const float* __restrict__ bias,
              float* __restrict__ out,
              const float* __restrict__ stats_in,  // prev layer sums (PRO)
              const float* __restrict__ gamma,
              const float* __restrict__ beta,
              float* __restrict__ stats,           // this layer sums (STATS)
              const int* __restrict__ gidx,
              const float* __restrict__ gw,
              const float* __restrict__ p2w,
              int ntiles) {
    extern __shared__ char sm[];
    constexpr int WROW   = 4 * KDIM + 32;   // [hi 2K][lo 2K][pad 32]
    constexpr int WLO    = 2 * KDIM;
    constexpr int OFF_A  = 128 * WROW;
    constexpr int APITCH = 80;
    constexpr int ALO    = 128 * APITCH;    // 10240
    constexpr int ABUF   = 2 * ALO;         // 20480 (hi+lo per buffer)
    constexpr int AUX    = OFF_A + 2 * ABUF;
    constexpr int NCH    = KDIM / 32;

    float* sBias = reinterpret_cast<float*>(sm + AUX);
    float* sAff  = reinterpret_cast<float*>(sm + AUX + 512);
    float* sSum  = reinterpret_cast<float*>(sm + AUX + 1536);
    float* sSq   = reinterpret_cast<float*>(sm + AUX + 2048);

    const int tid  = threadIdx.x;
    const int lane = tid & 31;
    const int w    = tid >> 5;
    const int wm   = w & 3;
    const int wn   = w >> 2;
    const int lg   = lane >> 2;
    const int lq   = lane & 3;
    const uint32_t sbase = smem_u32(sm);

    if (tid < 128) {
        sBias[tid] = bias ? bias[tid] : 0.0f;
        if (STATS) { sSum[tid] = 0.0f; sSq[tid] = 0.0f; }
        if (PRO) {
            const float invM = 1.0f / (float)MPTS;
            float mean = stats_in[tid] * invM;
            float var  = stats_in[128 + tid] * invM - mean * mean;
            float sc   = gamma[tid] * rsqrtf(var + 1e-5f);
            sAff[tid]       = sc;
            sAff[128 + tid] = fmaf(-mean, sc, beta[tid]);
        }
    }

    // ---- W -> smem bf16 hi/lo, k/k+8 interleaved within 16-k blocks ----
    for (int idx = tid; idx < 128 * KDIM; idx += 256) {
        int n = idx / KDIM, k = idx % KDIM;
        float v = W[n * wstride + k];
        __nv_bfloat16 h = __float2bfloat16(v);
        __nv_bfloat16 l = __float2bfloat16(v - __bfloat162float(h));
        int kk  = k & 15;
        int pos = ((kk & 7) >> 1) * 8 + ((kk >> 3) & 1) * 4 + (kk & 1) * 2;
        int off = n * WROW + (k >> 4) * 32 + pos;
        *reinterpret_cast<__nv_bfloat16*>(sm + off)       = h;
        *reinterpret_cast<__nv_bfloat16*>(sm + off + WLO) = l;
    }
    __syncthreads();

    // pair-local staging map: warps {wm, wm+4} own rows [wm*32, wm*32+32)
    const int pt   = wn * 32 + lane;        // 0..63 within the pair
    const int prow = wm * 32 + (pt >> 1);   // row this thread stages
    const int pq0  = (pt & 1) * 4;          // first 4-float quad (of 8)

    for (int t = blockIdx.x; t < ntiles; t += gridDim.x) {
        const float* Abase = A + (size_t)t * 128 * KDIM;

        float acc[2][8][4];
#pragma unroll
        for (int mi = 0; mi < 2; mi++)
#pragma unroll
            for (int nf = 0; nf < 8; nf++)
#pragma unroll
                for (int r = 0; r < 4; r++) acc[mi][nf][r] = 0.0f;

        // prefetch chunk 0
        float4 pf[4];
#pragma unroll
        for (int q = 0; q < 4; q++)
            pf[q] = *reinterpret_cast<const float4*>(
                Abase + (size_t)prow * KDIM + (pq0 + q) * 4);

        for (int kc = 0; kc < NCH; kc++) {
            const int bufo = OFF_A + (kc & 1) * ABUF;
            // ---- convert own rows -> smem bf16 hi/lo (buffer kc&1) ----
#pragma unroll
            for (int q = 0; q < 4; q++) {
                float4 f = pf[q];
                if (PRO) {
                    int c = kc * 32 + (pq0 + q) * 4;
                    f.x = gelu_exact(fmaf(sAff[c + 0], f.x, sAff[128 + c + 0]));
                    f.y = gelu_exact(fmaf(sAff[c + 1], f.y, sAff[128 + c + 1]));
                    f.z = gelu_exact(fmaf(sAff[c + 2], f.z, sAff[128 + c + 2]));
                    f.w = gelu_exact(fmaf(sAff[c + 3], f.w, sAff[128 + c + 3]));
                }
                uint32_t h0, l0, h1, l1;
                split2(f.x, f.y, h0, l0);
                split2(f.z, f.w, h1, l1);
                char* b = sm + bufo + prow * APITCH + (pq0 + q) * 8;
                *reinterpret_cast<uint2*>(b)       = make_uint2(h0, h1);
                *reinterpret_cast<uint2*>(b + ALO) = make_uint2(l0, l1);
            }
            BAR_PAIR(wm + 1);   // only the 2 warps sharing these rows sync

            // ---- issue next chunk's loads (hidden under MMA) ----
            if (kc + 1 < NCH) {
#pragma unroll
                for (int q = 0; q < 4; q++)
                    pf[q] = *reinterpret_cast<const float4*>(
                        Abase + (size_t)prow * KDIM + (kc + 1) * 32 + (pq0 + q) * 4);
            }

            // ---- MMA on current buffer (rows wm*32..+32 only) ----
            const uint32_t abase = sbase + bufo;
            const uint32_t lrow  = lane & 15;
            const uint32_t lkb   = (lane >> 4) << 4;
#pragma unroll
            for (int ks = 0; ks < 2; ks++) {
                uint32_t ah[2][4], al[2][4];
#pragma unroll
                for (int mi = 0; mi < 2; mi++) {
                    uint32_t ad = abase +
                        (wm * 32 + mi * 16 + lrow) * APITCH + ks * 32 + lkb;
                    LDMX4(ah[mi], ad);
                    LDMX4(al[mi], ad + ALO);
                }
#pragma unroll
                for (int nf = 0; nf < 8; nf++) {
                    const char* pw = sm + (wn * 64 + nf * 8 + lg) * WROW +
                                     (kc * 2 + ks) * 32 + lq * 8;
                    uint2 bh = *reinterpret_cast<const uint2*>(pw);
                    uint2 bl = *reinterpret_cast<const uint2*>(pw + WLO);
#pragma unroll
                    for (int mi = 0; mi < 2; mi++) {
                        MMA16816(acc[mi][nf], ah[mi], bh.x, bh.y);
                        MMA16816(acc[mi][nf], al[mi], bh.x, bh.y);
                        MMA16816(acc[mi][nf], ah[mi], bl.x, bl.y);
                    }
                }
            }
            // next convert writes the other buffer; pair barrier orders reuse
        }

        // ---- epilogue: bias (+gather), store, stats ----
        float cS[16], cQ[16];
        if (STATS) {
#pragma unroll
            for (int i = 0; i < 16; i++) { cS[i] = 0.0f; cQ[i] = 0.0f; }
        }
#pragma unroll
        for (int mi = 0; mi < 2; mi++) {
#pragma unroll
            for (int rh = 0; rh < 2; rh++) {
                int r = wm * 32 + mi * 16 + rh * 8 + lg;
                int m = t * 128 + r;
                int j0 = 0, j1 = 0, j2 = 0, gb = 0;
                float w0 = 0.f, w1 = 0.f, w2 = 0.f;
                if (GATHER) {
                    j0 = gidx[3 * m + 0]; j1 = gidx[3 * m + 1]; j2 = gidx[3 * m + 2];
                    w0 = gw[3 * m + 0];   w1 = gw[3 * m + 1];   w2 = gw[3 * m + 2];
                    gb = (m >> 12) << 17;
                }
                float* orow = out + (size_t)m * 128;
#pragma unroll
                for (int nf = 0; nf < 8; nf++) {
                    int c0 = wn * 64 + nf * 8 + lq * 2;
                    float v0 = acc[mi][nf][rh * 2 + 0] + sBias[c0];
                    float v1 = acc[mi][nf][rh * 2 + 1] + sBias[c0 + 1];
                    if (GATHER) {
                        float2 a0 = *reinterpret_cast<const float2*>(p2w + gb + (j0 << 7) + c0);
                        float2 a1 = *reinterpret_cast<const float2*>(p2w + gb + (j1 << 7) + c0);
                        float2 a2 = *reinterpret_cast<const float2*>(p2w + gb + (j2 << 7) + c0);
                        v0 += w0 * a0.x + w1 * a1.x + w2 * a2.x;
                        v1 += w0 * a0.y + w1 * a1.y + w2 * a2.y;
                    }
                    *reinterpret_cast<float2*>(orow + c0) = make_float2(v0, v1);
                    if (STATS) {
                        cS[nf * 2 + 0] += v0;
                        cS[nf * 2 + 1] += v1;
                        cQ[nf * 2 + 0] = fmaf(v0, v0, cQ[nf * 2 + 0]);
                        cQ[nf * 2 + 1] = fmaf(v1, v1, cQ[nf * 2 + 1]);
                    }
                }
            }
        }
        if (STATS) {
#pragma unroll
            for (int i = 0; i < 16; i++) {
                cS[i] += __shfl_xor_sync(0xffffffffu, cS[i], 4);
                cQ[i] += __shfl_xor_sync(0xffffffffu, cQ[i], 4);
                cS[i] += __shfl_xor_sync(0xffffffffu, cS[i], 8);
                cQ[i] += __shfl_xor_sync(0xffffffffu, cQ[i], 8);
                cS[i] += __shfl_xor_sync(0xffffffffu, cS[i], 16);
                cQ[i] += __shfl_xor_sync(0xffffffffu, cQ[i], 16);
            }
            if (lane < 4) {
#pragma unroll
                for (int nf = 0; nf < 8; nf++) {
                    int c = wn * 64 + nf * 8 + lane * 2;
                    atomicAdd(&sSum[c],     cS[nf * 2 + 0]);
                    atomicAdd(&sSum[c + 1], cS[nf * 2 + 1]);
                    atomicAdd(&sSq[c],      cQ[nf * 2 + 0]);
                    atomicAdd(&sSq[c + 1],  cQ[nf * 2 + 1]);
                }
            }
        }
    }

    if (STATS) {
        __syncthreads();
        if (tid < 128) {
            atomicAdd(&stats[tid],       sSum[tid]);
            atomicAdd(&stats[128 + tid], sSq[tid]);
        }
    }
}

// ---------------------------------------------------------------- launch
extern "C" void kernel_launch(void* const* d_in, const int* in_sizes, int n_in,
                              void* d_out, int out_size) {
    const float* xyz1    = (const float*)d_in[0];
    const float* xyz2    = (const float*)d_in[1];
    const float* points1 = (const float*)d_in[2];
    const float* points2 = (const float*)d_in[3];
    const float* fuse_w  = (const float*)d_in[4];
    const float* fuse_b  = (const float*)d_in[5];
    const float* fuse_g  = (const float*)d_in[6];
    const float* fuse_bt = (const float*)d_in[7];
    const float* w1      = (const float*)d_in[8];
    const float* b1      = (const float*)d_in[9];
    const float* g1      = (const float*)d_in[10];
    const float* bt1     = (const float*)d_in[11];
    const float* w2      = (const float*)d_in[12];
    const float* b2      = (const float*)d_in[13];
    const float* g2      = (const float*)d_in[14];
    const float* bt2     = (const float*)d_in[15];
    float* out = (float*)d_out;

    float *p_p2w, *p_t0, *p_t1, *p_t2, *p_w, *p_stats;
    int* p_idx;
    cudaGetSymbolAddress((void**)&p_p2w,   g_p2w);
    cudaGetSymbolAddress((void**)&p_t0,    g_t0);
    cudaGetSymbolAddress((void**)&p_t1,    g_t1);
    cudaGetSymbolAddress((void**)&p_t2,    g_t2);
    cudaGetSymbolAddress((void**)&p_idx,   g_idx);
    cudaGetSymbolAddress((void**)&p_w,     g_w);
    cudaGetSymbolAddress((void**)&p_stats, g_stats);

    // dyn smem: W(128*WROW) + 2 A buffers + 2560 aux
    constexpr int SMEM_K128 = 128 * (4 * 128 + 32) + 2 * 20480 + 2560;  // 113152
    constexpr int SMEM_K256 = 128 * (4 * 256 + 32) + 2 * 20480 + 2560;  // 178688
    static bool attr_done = false;
    if (!attr_done) {
        cudaFuncSetAttribute(mma_gemm<256, false, false, false>,
                             cudaFuncAttributeMaxDynamicSharedMemorySize, SMEM_K256);
        cudaFuncSetAttribute(mma_gemm<128, false, true, true>,
                             cudaFuncAttributeMaxDynamicSharedMemorySize, SMEM_K128);
        cudaFuncSetAttribute(mma_gemm<128, true, false, true>,
                             cudaFuncAttributeMaxDynamicSharedMemorySize, SMEM_K128);
        attr_done = true;
    }

    // knn + stat zeroing
    knn3_kernel<<<Bn * 32, 128>>>(xyz1, xyz2, p_idx, p_w, p_stats);

    // P2W = points2 @ fuse_w[:,128:384]^T   (16384 x 128, K=256)
    mma_gemm<256, false, false, false><<<MSRC / 128, 256, SMEM_K256>>>(
        points2, fuse_w + 128, 384, nullptr, p_p2w,
        nullptr, nullptr, nullptr, nullptr, nullptr, nullptr, nullptr, MSRC / 128);

    // t0 = points1 @ fuse_w[:,0:128]^T + fuse_b + gather(P2W) ; stats0
    mma_gemm<128, false, true, true><<<296, 256, SMEM_K128>>>(
        points1, fuse_w, 384, fuse_b, p_t0,
        nullptr, nullptr, nullptr, p_stats + 0, p_idx, p_w, p_p2w, MPTS / 128);

    // t1 = gelu(bn0(t0)) @ w1^T + b1 ; stats1   (aff computed in-kernel)
    mma_gemm<128, true, false, true><<<296, 256, SMEM_K128>>>(
        p_t0, w1, 128, b1, p_t1,
        p_stats + 0, fuse_g, fuse_bt, p_stats + 256, nullptr, nullptr, nullptr, MPTS / 128);

    // t2 = gelu(bn1(t1)) @ w2^T + b2 ; stats2
    mma_gemm<128, true, false, true><<<296, 256, SMEM_K128>>>(
        p_t1, w2, 128, b2, p_t2,
        p_stats + 256, g1, bt1, p_stats + 512, nullptr, nullptr, nullptr, MPTS / 128);

    // out = gelu(bn2(t2) + gelu(bn0(t0)))  (both affines computed in-kernel)
    final_kernel<<<(MPTS * 128 / 4) / 256, 256>>>(
        p_t0, p_t2, p_stats + 0, fuse_g, fuse_bt, p_stats + 512, g2, bt2, out);
}